// round 1
// baseline (speedup 1.0000x reference)
#include <cuda_runtime.h>
#include <math.h>
#include <stdint.h>

#define N_NODES 100000
#define N_EDGES 1000000

// ---------------- device scratch (module-static, no runtime alloc) ----------------
__device__ int   g_is64;
__device__ __align__(16) int   g_src[N_EDGES];
__device__ __align__(16) int   g_dst[N_EDGES];
__device__ __align__(16) int   g_degi[N_NODES];
__device__ __align__(16) float g_dis[N_NODES];
__device__ __align__(16) int   g_rowptr[N_NODES + 1];
__device__ __align__(16) int   g_fill[N_NODES];
__device__ __align__(16) int   g_col[N_EDGES];
__device__ __align__(16) float g_wv[N_EDGES];
__device__ __align__(16) float g_bnsum[128];
__device__ __align__(16) float g_bnsq[128];
__device__ __align__(16) float g_bns[128];
__device__ __align__(16) float g_bnt[128];
__device__ __align__(16) float g_bufh[N_NODES * 64];
__device__ __align__(16) float g_bufp0[N_NODES * 64];
__device__ __align__(16) float g_bufp1[N_NODES * 64];
__device__ __align__(16) float g_bufo[N_NODES * 64];
__device__ __align__(16) float g_bufa[N_NODES * 128];

// ---------------- helpers ----------------
__device__ __forceinline__ float gelu_f(float v) {
    return 0.5f * v * (1.0f + erff(v * 0.70710678118654752440f));
}

// edge_index dtype detection: if int64, every odd 32-bit word (hi word of a
// small nonnegative value) is 0. For real int32 data those are random node ids.
__global__ void detect_k(const int* __restrict__ ei) {
    __shared__ int anynz;
    if (threadIdx.x == 0) anynz = 0;
    __syncthreads();
    if (ei[threadIdx.x * 2 + 1] != 0) anynz = 1;
    __syncthreads();
    if (threadIdx.x == 0) g_is64 = (anynz == 0) ? 1 : 0;
}

__global__ void zero_pre_k() {
    int i = blockIdx.x * blockDim.x + threadIdx.x;
    if (i < N_NODES) g_degi[i] = 0;
    if (i < 128) { g_bnsum[i] = 0.f; g_bnsq[i] = 0.f; }
}

__global__ void convert_k(const void* __restrict__ ei) {
    int e = blockIdx.x * blockDim.x + threadIdx.x;
    if (e >= N_EDGES) return;
    int s, d;
    if (g_is64) {
        const long long* p = (const long long*)ei;
        s = (int)p[e];
        d = (int)p[N_EDGES + e];
    } else {
        const int* p = (const int*)ei;
        s = p[e];
        d = p[N_EDGES + e];
    }
    g_src[e] = s;
    g_dst[e] = d;
    atomicAdd(&g_degi[d], 1);
}

__global__ void dis_k() {
    int i = blockIdx.x * blockDim.x + threadIdx.x;
    if (i >= N_NODES) return;
    int d = g_degi[i];
    g_dis[i] = (d > 0) ? rsqrtf((float)d) : 0.f;
}

// single-block exclusive scan of g_degi -> g_rowptr / g_fill
__global__ void scan_k() {
    __shared__ int sh[1024];
    __shared__ int soff;
    int t = threadIdx.x;
    if (t == 0) soff = 0;
    __syncthreads();
    for (int base = 0; base < N_NODES; base += 1024) {
        int i = base + t;
        int v = (i < N_NODES) ? g_degi[i] : 0;
        sh[t] = v;
        __syncthreads();
        for (int off = 1; off < 1024; off <<= 1) {
            int tv = (t >= off) ? sh[t - off] : 0;
            __syncthreads();
            sh[t] += tv;
            __syncthreads();
        }
        if (i < N_NODES) {
            int ex = soff + sh[t] - v;
            g_rowptr[i] = ex;
            g_fill[i]   = ex;
        }
        __syncthreads();
        if (t == 0) soff += sh[1023];
        __syncthreads();
    }
    if (t == 0) g_rowptr[N_NODES] = soff;
}

__global__ void csrfill_k() {
    int e = blockIdx.x * blockDim.x + threadIdx.x;
    if (e >= N_EDGES) return;
    int s = g_src[e], d = g_dst[e];
    int pos = atomicAdd(&g_fill[d], 1);
    g_col[pos] = s;
    g_wv[pos]  = g_dis[s] * g_dis[d];
}

// BatchNorm statistics over nodes (columns of x, IN_DIM=128)
__global__ void bn_stats_k(const float* __restrict__ x) {
    int col = threadIdx.x & 127;
    int r = blockIdx.x * 2 + (threadIdx.x >> 7);
    float s = 0.f, q = 0.f;
    for (; r < N_NODES; r += gridDim.x * 2) {
        float v = x[(size_t)r * 128 + col];
        s += v;
        q += v * v;
    }
    atomicAdd(&g_bnsum[col], s);
    atomicAdd(&g_bnsq[col], q);
}

__global__ void bn_final_k(const float* __restrict__ gamma, const float* __restrict__ beta) {
    int c = threadIdx.x;
    float mean = g_bnsum[c] * (1.0f / N_NODES);
    float var  = g_bnsq[c] * (1.0f / N_NODES) - mean * mean;
    float s = gamma[c] * rsqrtf(var + 1e-5f);
    g_bns[c] = s;
    g_bnt[c] = beta[c] - mean * s;
}

// CSR propagation: out[dst] = sum_e norm_e * in[src_e], 64 feats, warp per node.
__global__ void __launch_bounds__(256) prop_k(const float* __restrict__ in,
                                              float* __restrict__ out) {
    int node = (blockIdx.x << 3) + (threadIdx.x >> 5);
    if (node >= N_NODES) return;
    int lane = threadIdx.x & 31;
    int beg = g_rowptr[node], end = g_rowptr[node + 1];
    float a0 = 0.f, a1 = 0.f;
    for (int e = beg; e < end; e++) {
        int s   = g_col[e];
        float w = g_wv[e];
        const float* row = in + (size_t)s * 64;
        a0 = fmaf(w, __ldg(row + lane), a0);
        a1 = fmaf(w, __ldg(row + lane + 32), a1);
    }
    float* orow = out + (size_t)node * 64;
    orow[lane]      = a0;
    orow[lane + 32] = a1;
}

// Tiled SIMT fp32 GEMM: C[N_NODES, NOUT] (+)= act(A[N_NODES, KD] @ W[KD, NOUT] + bias)
// BNA: apply per-input-column affine (fused BatchNorm) while loading A.
template <int KD, int NOUT, bool ACC, bool BIAS, bool ACT, bool BNA>
__global__ void __launch_bounds__(256) gemm_k(const float* __restrict__ A,
                                              const float* __restrict__ W,
                                              const float* __restrict__ bias,
                                              float* __restrict__ C) {
    constexpr int TN = NOUT / 16;
    __shared__ float As[128][17];
    __shared__ __align__(16) float Ws[16][NOUT];
    int tid = threadIdx.x;
    int tx = tid & 15, ty = tid >> 4;
    int m0 = blockIdx.x * 128;

    float acc[8][TN];
#pragma unroll
    for (int i = 0; i < 8; i++)
#pragma unroll
        for (int j = 0; j < TN; j++) acc[i][j] = 0.f;

    for (int k0 = 0; k0 < KD; k0 += 16) {
        // load 128x16 A tile (float4, coalesced), optional fused BN affine
#pragma unroll
        for (int p = 0; p < 2; p++) {
            int r  = p * 64 + (tid >> 2);
            int kq = (tid & 3) * 4;
            int gr = m0 + r;
            float4 v = make_float4(0.f, 0.f, 0.f, 0.f);
            if (gr < N_NODES) v = *(const float4*)(A + (size_t)gr * KD + k0 + kq);
            if (BNA) {
                int kc = k0 + kq;
                v.x = v.x * g_bns[kc]     + g_bnt[kc];
                v.y = v.y * g_bns[kc + 1] + g_bnt[kc + 1];
                v.z = v.z * g_bns[kc + 2] + g_bnt[kc + 2];
                v.w = v.w * g_bns[kc + 3] + g_bnt[kc + 3];
            }
            As[r][kq]     = v.x;
            As[r][kq + 1] = v.y;
            As[r][kq + 2] = v.z;
            As[r][kq + 3] = v.w;
        }
        // load 16xNOUT W tile
#pragma unroll
        for (int q = 0; q < NOUT / 64; q++) {
            int idx = q * 256 + tid;
            int kr  = idx / (NOUT / 4);
            int kc  = (idx % (NOUT / 4)) * 4;
            *(float4*)&Ws[kr][kc] = *(const float4*)(W + (size_t)(k0 + kr) * NOUT + kc);
        }
        __syncthreads();
#pragma unroll
        for (int kk = 0; kk < 16; kk++) {
            float a[8];
#pragma unroll
            for (int i = 0; i < 8; i++) a[i] = As[ty * 8 + i][kk];
            float b[TN];
#pragma unroll
            for (int j = 0; j < TN; j += 4) {
                float4 w = *(const float4*)&Ws[kk][tx * TN + j];
                b[j] = w.x; b[j + 1] = w.y; b[j + 2] = w.z; b[j + 3] = w.w;
            }
#pragma unroll
            for (int i = 0; i < 8; i++)
#pragma unroll
                for (int j = 0; j < TN; j++) acc[i][j] = fmaf(a[i], b[j], acc[i][j]);
        }
        __syncthreads();
    }

    // epilogue
#pragma unroll
    for (int i = 0; i < 8; i++) {
        int gr = m0 + ty * 8 + i;
        if (gr >= N_NODES) continue;
#pragma unroll
        for (int j = 0; j < TN; j += 4) {
            int c = tx * TN + j;
            float4 v = make_float4(acc[i][j], acc[i][j + 1], acc[i][j + 2], acc[i][j + 3]);
            if (ACC) {
                float4 old = *(const float4*)(C + (size_t)gr * NOUT + c);
                v.x += old.x; v.y += old.y; v.z += old.z; v.w += old.w;
            }
            if (BIAS) {
                v.x += bias[c]; v.y += bias[c + 1]; v.z += bias[c + 2]; v.w += bias[c + 3];
            }
            if (ACT) {
                v.x = gelu_f(v.x); v.y = gelu_f(v.y); v.z = gelu_f(v.z); v.w = gelu_f(v.w);
            }
            *(float4*)(C + (size_t)gr * NOUT + c) = v;
        }
    }
}

// ---------------- host launcher ----------------
extern "C" void kernel_launch(void* const* d_in, const int* in_sizes, int n_in,
                              void* d_out, int out_size) {
    const float* x     = (const float*)d_in[0];
    const void*  ei    = d_in[1];
    const float* gamma = (const float*)d_in[2];
    const float* beta  = (const float*)d_in[3];
    const float* W1 = (const float*)d_in[4];  const float* b1  = (const float*)d_in[5];
    const float* T1 = (const float*)d_in[6];  const float* t1b = (const float*)d_in[7];
    const float* W2 = (const float*)d_in[8];  const float* b2  = (const float*)d_in[9];
    const float* T2 = (const float*)d_in[10]; const float* t2b = (const float*)d_in[11];
    const float* W3 = (const float*)d_in[12]; const float* b3  = (const float*)d_in[13];
    const float* W4 = (const float*)d_in[14]; const float* b4  = (const float*)d_in[15];
    float* out = (float*)d_out;

    float *bufh, *bufp0, *bufp1, *bufo, *bufa;
    cudaGetSymbolAddress((void**)&bufh,  g_bufh);
    cudaGetSymbolAddress((void**)&bufp0, g_bufp0);
    cudaGetSymbolAddress((void**)&bufp1, g_bufp1);
    cudaGetSymbolAddress((void**)&bufo,  g_bufo);
    cudaGetSymbolAddress((void**)&bufa,  g_bufa);

    const int EB = (N_EDGES + 255) / 256;   // 3907
    const int NB = (N_NODES + 255) / 256;   // 391
    const int GB = (N_NODES + 127) / 128;   // 782
    const int PB = N_NODES / 8;             // 12500 (warp per node, 8 warps/block)

    // ---- graph preprocessing + BN stats ----
    detect_k<<<1, 256>>>((const int*)ei);
    zero_pre_k<<<NB, 256>>>();
    convert_k<<<EB, 256>>>(ei);
    dis_k<<<NB, 256>>>();
    scan_k<<<1, 1024>>>();
    csrfill_k<<<EB, 256>>>();
    bn_stats_k<<<512, 256>>>(x);
    bn_final_k<<<1, 128>>>(gamma, beta);

    // ---- layer 1: h = gelu(BN(x) @ W1 + b1) ----
    gemm_k<128, 64, false, true, true, true><<<GB, 256>>>(x, W1, b1, bufh);

    // ---- TAGConv 1 ----
    gemm_k<64, 64, false, false, false, false><<<GB, 256>>>(bufh, T1, nullptr, bufo);
    prop_k<<<PB, 256>>>(bufh, bufp0);
    gemm_k<64, 64, true, false, false, false><<<GB, 256>>>(bufp0, T1 + 4096, nullptr, bufo);
    prop_k<<<PB, 256>>>(bufp0, bufp1);
    gemm_k<64, 64, true, false, false, false><<<GB, 256>>>(bufp1, T1 + 8192, nullptr, bufo);
    prop_k<<<PB, 256>>>(bufp1, bufp0);
    gemm_k<64, 64, true, true, true, false><<<GB, 256>>>(bufp0, T1 + 12288, t1b, bufo);

    // ---- layer 2: h = gelu(o @ W2 + b2) ----
    gemm_k<64, 64, false, true, true, false><<<GB, 256>>>(bufo, W2, b2, bufh);

    // ---- TAGConv 2 ----
    gemm_k<64, 64, false, false, false, false><<<GB, 256>>>(bufh, T2, nullptr, bufo);
    prop_k<<<PB, 256>>>(bufh, bufp0);
    gemm_k<64, 64, true, false, false, false><<<GB, 256>>>(bufp0, T2 + 4096, nullptr, bufo);
    prop_k<<<PB, 256>>>(bufp0, bufp1);
    gemm_k<64, 64, true, false, false, false><<<GB, 256>>>(bufp1, T2 + 8192, nullptr, bufo);
    prop_k<<<PB, 256>>>(bufp1, bufp0);
    gemm_k<64, 64, true, true, true, false><<<GB, 256>>>(bufp0, T2 + 12288, t2b, bufo);

    // ---- layer 3: a = gelu(concat(x, h) @ W3 + b3), split along K ----
    gemm_k<128, 128, false, false, false, false><<<GB, 256>>>(x, W3, nullptr, bufa);
    gemm_k<64, 128, true, true, true, false><<<GB, 256>>>(bufo, W3 + 128 * 128, b3, bufa);

    // ---- layer 4: out = a @ W4 + b4 ----
    gemm_k<128, 64, false, true, false, false><<<GB, 256>>>(bufa, W4, b4, out);
}

// round 2
// speedup vs baseline: 1.4954x; 1.4954x over previous
#include <cuda_runtime.h>
#include <math.h>
#include <stdint.h>

#define N_NODES 100000
#define N_EDGES 1000000

// ---------------- device scratch (module-static, no runtime alloc) ----------------
__device__ int   g_is64;
__device__ __align__(16) int   g_src[N_EDGES];
__device__ __align__(16) int   g_dst[N_EDGES];
__device__ __align__(16) int   g_degi[N_NODES];
__device__ __align__(16) float g_dis[N_NODES];
__device__ __align__(16) int   g_rowptr[N_NODES + 1];
__device__ __align__(16) int   g_fill[N_NODES];
__device__ __align__(16) int   g_col[N_EDGES];
__device__ __align__(16) float g_wv[N_EDGES];
__device__ __align__(16) float g_bnsum[128];
__device__ __align__(16) float g_bnsq[128];
__device__ __align__(16) float g_bns[128];
__device__ __align__(16) float g_bnt[128];
__device__ __align__(16) float g_bufh[N_NODES * 64];
__device__ __align__(16) float g_bufp0[N_NODES * 64];
__device__ __align__(16) float g_bufp1[N_NODES * 64];
__device__ __align__(16) float g_bufp2[N_NODES * 64];
__device__ __align__(16) float g_bufo[N_NODES * 64];
__device__ __align__(16) float g_bufa[N_NODES * 128];

// ---------------- helpers ----------------
__device__ __forceinline__ float gelu_f(float v) {
    return 0.5f * v * (1.0f + erff(v * 0.70710678118654752440f));
}

__device__ __forceinline__ uint32_t f2tf(float f) {
    uint32_t r;
    asm("cvt.rna.tf32.f32 %0, %1;" : "=r"(r) : "f"(f));
    return r;
}

__device__ __forceinline__ void mma8(float d[4], const uint32_t a[4],
                                     uint32_t b0, uint32_t b1) {
    asm volatile(
        "mma.sync.aligned.m16n8k8.row.col.f32.tf32.tf32.f32 "
        "{%0,%1,%2,%3}, {%4,%5,%6,%7}, {%8,%9}, {%0,%1,%2,%3};"
        : "+f"(d[0]), "+f"(d[1]), "+f"(d[2]), "+f"(d[3])
        : "r"(a[0]), "r"(a[1]), "r"(a[2]), "r"(a[3]), "r"(b0), "r"(b1));
}

// edge_index dtype detection: if int64, every odd 32-bit word is 0.
__global__ void detect_k(const int* __restrict__ ei) {
    __shared__ int anynz;
    if (threadIdx.x == 0) anynz = 0;
    __syncthreads();
    if (ei[threadIdx.x * 2 + 1] != 0) anynz = 1;
    __syncthreads();
    if (threadIdx.x == 0) g_is64 = (anynz == 0) ? 1 : 0;
}

__global__ void zero_pre_k() {
    int i = blockIdx.x * blockDim.x + threadIdx.x;
    if (i < N_NODES) g_degi[i] = 0;
    if (i < 128) { g_bnsum[i] = 0.f; g_bnsq[i] = 0.f; }
}

__global__ void convert_k(const void* __restrict__ ei) {
    int e = blockIdx.x * blockDim.x + threadIdx.x;
    if (e >= N_EDGES) return;
    int s, d;
    if (g_is64) {
        const long long* p = (const long long*)ei;
        s = (int)p[e];
        d = (int)p[N_EDGES + e];
    } else {
        const int* p = (const int*)ei;
        s = p[e];
        d = p[N_EDGES + e];
    }
    g_src[e] = s;
    g_dst[e] = d;
    atomicAdd(&g_degi[d], 1);
}

__global__ void dis_k() {
    int i = blockIdx.x * blockDim.x + threadIdx.x;
    if (i >= N_NODES) return;
    int d = g_degi[i];
    g_dis[i] = (d > 0) ? rsqrtf((float)d) : 0.f;
}

// single-block exclusive scan with warp shuffles
__global__ void scan_k() {
    __shared__ int wsum[32];
    __shared__ int soff;
    int t = threadIdx.x, lane = t & 31, w = t >> 5;
    if (t == 0) soff = 0;
    __syncthreads();
    for (int base = 0; base < N_NODES; base += 1024) {
        int i = base + t;
        int v = (i < N_NODES) ? g_degi[i] : 0;
        int x = v;
#pragma unroll
        for (int off = 1; off < 32; off <<= 1) {
            int y = __shfl_up_sync(0xffffffffu, x, off);
            if (lane >= off) x += y;
        }
        if (lane == 31) wsum[w] = x;
        __syncthreads();
        if (w == 0) {
            int s = wsum[lane];
#pragma unroll
            for (int off = 1; off < 32; off <<= 1) {
                int y = __shfl_up_sync(0xffffffffu, s, off);
                if (lane >= off) s += y;
            }
            wsum[lane] = s;
        }
        __syncthreads();
        int pre = soff + (w ? wsum[w - 1] : 0) + x - v;
        if (i < N_NODES) { g_rowptr[i] = pre; g_fill[i] = pre; }
        int tot = wsum[31];
        __syncthreads();
        if (t == 0) soff += tot;
        __syncthreads();
    }
    if (threadIdx.x == 0) g_rowptr[N_NODES] = soff;
}

__global__ void csrfill_k() {
    int e = blockIdx.x * blockDim.x + threadIdx.x;
    if (e >= N_EDGES) return;
    int s = g_src[e], d = g_dst[e];
    int pos = atomicAdd(&g_fill[d], 1);
    g_col[pos] = s;
    g_wv[pos]  = g_dis[s] * g_dis[d];
}

__global__ void bn_stats_k(const float* __restrict__ x) {
    int col = threadIdx.x & 127;
    int r = blockIdx.x * 2 + (threadIdx.x >> 7);
    float s = 0.f, q = 0.f;
    for (; r < N_NODES; r += gridDim.x * 2) {
        float v = x[(size_t)r * 128 + col];
        s += v;
        q += v * v;
    }
    atomicAdd(&g_bnsum[col], s);
    atomicAdd(&g_bnsq[col], q);
}

__global__ void bn_final_k(const float* __restrict__ gamma, const float* __restrict__ beta) {
    int c = threadIdx.x;
    float mean = g_bnsum[c] * (1.0f / N_NODES);
    float var  = g_bnsq[c] * (1.0f / N_NODES) - mean * mean;
    float s = gamma[c] * rsqrtf(var + 1e-5f);
    g_bns[c] = s;
    g_bnt[c] = beta[c] - mean * s;
}

// CSR propagation: out[dst] = sum_e norm_e * in[src_e], 64 feats, warp per node.
__global__ void __launch_bounds__(256) prop_k(const float* __restrict__ in,
                                              float* __restrict__ out) {
    int node = (blockIdx.x << 3) + (threadIdx.x >> 5);
    if (node >= N_NODES) return;
    int lane = threadIdx.x & 31;
    int beg = g_rowptr[node], end = g_rowptr[node + 1];
    float a0 = 0.f, a1 = 0.f;
    for (int e = beg; e < end; e++) {
        int s   = g_col[e];
        float w = g_wv[e];
        const float* row = in + (size_t)s * 64;
        a0 = fmaf(w, __ldg(row + lane), a0);
        a1 = fmaf(w, __ldg(row + lane + 32), a1);
    }
    float* orow = out + (size_t)node * 64;
    orow[lane]      = a0;
    orow[lane + 32] = a1;
}

// ---------------- tensor-core tf32 GEMM (3xTF32 split for fp32 accuracy) ------------
// C[N_NODES, NOUT] = act( concat_segs(A)[N_NODES, KD] @ W[KD, NOUT] + bias )
// Up to 4 A segments (row-major, widths multiple of 32). 128 rows per block,
// 256 threads = 8 warps in a 4(m) x 2(n) grid; warp tile 32 x NOUT/2.
template <int KD, int NOUT, bool ACT, bool BNA>
__global__ void __launch_bounds__(256) tgemm_k(
    const float* __restrict__ p0, const float* __restrict__ p1,
    const float* __restrict__ p2, const float* __restrict__ p3,
    int w0, int w1, int w2,
    const float* __restrict__ W, const float* __restrict__ bias,
    float* __restrict__ C) {
    __shared__ float As[128][36];
    __shared__ __align__(16) float Ws[32][NOUT + 4];

    constexpr int NT = NOUT / 16;  // 8-wide n tiles per warp
    int tid = threadIdx.x;
    int lane = tid & 31, wid = tid >> 5;
    int gid = lane >> 2, tg = lane & 3;
    int warp_m = wid & 3, warp_n = wid >> 2;
    int Rm = warp_m * 32;
    int Cn = warp_n * (NOUT / 2);
    int m0 = blockIdx.x * 128;

    float d[2][NT][4];
#pragma unroll
    for (int mt = 0; mt < 2; mt++)
#pragma unroll
        for (int nt = 0; nt < NT; nt++)
#pragma unroll
            for (int q = 0; q < 4; q++) d[mt][nt][q] = 0.f;

    for (int k0 = 0; k0 < KD; k0 += 32) {
        // segment select for this 32-wide chunk
        const float* Ap = p0; int Aw = w0; int cum = 0;
        if (k0 >= w0)            { Ap = p1; Aw = w1; cum = w0; }
        if (k0 >= w0 + w1)       { Ap = p2; Aw = w2; cum = w0 + w1; }
        if (k0 >= w0 + w1 + w2)  { Ap = p3; Aw = KD - (w0 + w1 + w2); cum = w0 + w1 + w2; }
        int kloc = k0 - cum;

        // load 128x32 A tile (coalesced float4)
#pragma unroll
        for (int pass = 0; pass < 4; pass++) {
            int r  = pass * 32 + (tid >> 3);
            int c4 = (tid & 7) * 4;
            int gr = m0 + r;
            float4 v = make_float4(0.f, 0.f, 0.f, 0.f);
            if (gr < N_NODES) v = *(const float4*)(Ap + (size_t)gr * Aw + kloc + c4);
            if (BNA) {
                int kc = k0 + c4;
                v.x = v.x * g_bns[kc]     + g_bnt[kc];
                v.y = v.y * g_bns[kc + 1] + g_bnt[kc + 1];
                v.z = v.z * g_bns[kc + 2] + g_bnt[kc + 2];
                v.w = v.w * g_bns[kc + 3] + g_bnt[kc + 3];
            }
            As[r][c4]     = v.x;
            As[r][c4 + 1] = v.y;
            As[r][c4 + 2] = v.z;
            As[r][c4 + 3] = v.w;
        }
        // load 32xNOUT W tile
#pragma unroll
        for (int idx = tid; idx < 32 * NOUT / 4; idx += 256) {
            int kr = idx / (NOUT / 4);
            int c4 = (idx % (NOUT / 4)) * 4;
            *(float4*)&Ws[kr][c4] = *(const float4*)(W + (size_t)(k0 + kr) * NOUT + c4);
        }
        __syncthreads();

#pragma unroll
        for (int ks = 0; ks < 4; ks++) {
            int kk = ks * 8;
            uint32_t ah[2][4], al[2][4];
#pragma unroll
            for (int mt = 0; mt < 2; mt++) {
                int rb = Rm + mt * 16;
                float f0 = As[rb + gid][kk + tg];
                float f1 = As[rb + gid + 8][kk + tg];
                float f2 = As[rb + gid][kk + tg + 4];
                float f3 = As[rb + gid + 8][kk + tg + 4];
                ah[mt][0] = f2tf(f0); al[mt][0] = f2tf(f0 - __uint_as_float(ah[mt][0]));
                ah[mt][1] = f2tf(f1); al[mt][1] = f2tf(f1 - __uint_as_float(ah[mt][1]));
                ah[mt][2] = f2tf(f2); al[mt][2] = f2tf(f2 - __uint_as_float(ah[mt][2]));
                ah[mt][3] = f2tf(f3); al[mt][3] = f2tf(f3 - __uint_as_float(ah[mt][3]));
            }
#pragma unroll
            for (int nt = 0; nt < NT; nt++) {
                int col = Cn + nt * 8 + gid;
                float g0 = Ws[kk + tg][col];
                float g1 = Ws[kk + tg + 4][col];
                uint32_t bh0 = f2tf(g0), bh1 = f2tf(g1);
                uint32_t bl0 = f2tf(g0 - __uint_as_float(bh0));
                uint32_t bl1 = f2tf(g1 - __uint_as_float(bh1));
#pragma unroll
                for (int mt = 0; mt < 2; mt++) {
                    mma8(d[mt][nt], ah[mt], bh0, bh1);
                    mma8(d[mt][nt], al[mt], bh0, bh1);
                    mma8(d[mt][nt], ah[mt], bl0, bl1);
                }
            }
        }
        __syncthreads();
    }

    // epilogue
#pragma unroll
    for (int mt = 0; mt < 2; mt++) {
#pragma unroll
        for (int nt = 0; nt < NT; nt++) {
            int col = Cn + nt * 8 + tg * 2;
            float bx = bias[col], by = bias[col + 1];
            int r0 = m0 + Rm + mt * 16 + gid;
            int r1 = r0 + 8;
            float v0 = d[mt][nt][0] + bx, v1 = d[mt][nt][1] + by;
            float v2 = d[mt][nt][2] + bx, v3 = d[mt][nt][3] + by;
            if (ACT) { v0 = gelu_f(v0); v1 = gelu_f(v1); v2 = gelu_f(v2); v3 = gelu_f(v3); }
            if (r0 < N_NODES) *(float2*)(C + (size_t)r0 * NOUT + col) = make_float2(v0, v1);
            if (r1 < N_NODES) *(float2*)(C + (size_t)r1 * NOUT + col) = make_float2(v2, v3);
        }
    }
}

// ---------------- host launcher ----------------
extern "C" void kernel_launch(void* const* d_in, const int* in_sizes, int n_in,
                              void* d_out, int out_size) {
    const float* x     = (const float*)d_in[0];
    const void*  ei    = d_in[1];
    const float* gamma = (const float*)d_in[2];
    const float* beta  = (const float*)d_in[3];
    const float* W1 = (const float*)d_in[4];  const float* b1  = (const float*)d_in[5];
    const float* T1 = (const float*)d_in[6];  const float* t1b = (const float*)d_in[7];
    const float* W2 = (const float*)d_in[8];  const float* b2  = (const float*)d_in[9];
    const float* T2 = (const float*)d_in[10]; const float* t2b = (const float*)d_in[11];
    const float* W3 = (const float*)d_in[12]; const float* b3  = (const float*)d_in[13];
    const float* W4 = (const float*)d_in[14]; const float* b4  = (const float*)d_in[15];
    float* out = (float*)d_out;

    float *bufh, *bufp0, *bufp1, *bufp2, *bufo, *bufa;
    cudaGetSymbolAddress((void**)&bufh,  g_bufh);
    cudaGetSymbolAddress((void**)&bufp0, g_bufp0);
    cudaGetSymbolAddress((void**)&bufp1, g_bufp1);
    cudaGetSymbolAddress((void**)&bufp2, g_bufp2);
    cudaGetSymbolAddress((void**)&bufo,  g_bufo);
    cudaGetSymbolAddress((void**)&bufa,  g_bufa);

    const int EB = (N_EDGES + 255) / 256;
    const int NB = (N_NODES + 255) / 256;
    const int GB = (N_NODES + 127) / 128;   // 782
    const int PB = N_NODES / 8;             // 12500

    // ---- graph preprocessing + BN stats ----
    detect_k<<<1, 256>>>((const int*)ei);
    zero_pre_k<<<NB, 256>>>();
    convert_k<<<EB, 256>>>(ei);
    dis_k<<<NB, 256>>>();
    scan_k<<<1, 1024>>>();
    csrfill_k<<<EB, 256>>>();
    bn_stats_k<<<512, 256>>>(x);
    bn_final_k<<<1, 128>>>(gamma, beta);

    // ---- layer 1: h = gelu(BN(x) @ W1 + b1) ----
    tgemm_k<128, 64, true, true><<<GB, 256>>>(x, x, x, x, 128, 0, 0, W1, b1, bufh);

    // ---- TAGConv 1 (props then ONE fused K=256 GEMM) ----
    prop_k<<<PB, 256>>>(bufh, bufp0);
    prop_k<<<PB, 256>>>(bufp0, bufp1);
    prop_k<<<PB, 256>>>(bufp1, bufp2);
    tgemm_k<256, 64, true, false><<<GB, 256>>>(bufh, bufp0, bufp1, bufp2,
                                               64, 64, 64, T1, t1b, bufo);

    // ---- layer 2: h = gelu(o @ W2 + b2) ----
    tgemm_k<64, 64, true, false><<<GB, 256>>>(bufo, bufo, bufo, bufo, 64, 0, 0, W2, b2, bufh);

    // ---- TAGConv 2 ----
    prop_k<<<PB, 256>>>(bufh, bufp0);
    prop_k<<<PB, 256>>>(bufp0, bufp1);
    prop_k<<<PB, 256>>>(bufp1, bufp2);
    tgemm_k<256, 64, true, false><<<GB, 256>>>(bufh, bufp0, bufp1, bufp2,
                                               64, 64, 64, T2, t2b, bufo);

    // ---- layer 3: a = gelu(concat(x, h) @ W3 + b3), 2-segment K=192 ----
    tgemm_k<192, 128, true, false><<<GB, 256>>>(x, bufo, bufo, bufo, 128, 64, 0, W3, b3, bufa);

    // ---- layer 4: out = a @ W4 + b4 ----
    tgemm_k<128, 64, false, false><<<GB, 256>>>(bufa, bufa, bufa, bufa, 128, 0, 0, W4, b4, out);
}

// round 3
// speedup vs baseline: 1.8092x; 1.2099x over previous
#include <cuda_runtime.h>
#include <cuda_fp16.h>
#include <cuda_bf16.h>
#include <math.h>
#include <stdint.h>

#define N_NODES 100000
#define N_EDGES 1000000

// ---------------- device scratch ----------------
__device__ int   g_is64;
__device__ __align__(16) int   g_src[N_EDGES];
__device__ __align__(16) int   g_dst[N_EDGES];
__device__ __align__(16) int   g_degi[N_NODES];
__device__ __align__(16) float g_dis[N_NODES];
__device__ __align__(16) int   g_rowptr[N_NODES + 1];
__device__ __align__(16) int   g_fill[N_NODES];
__device__ __align__(16) int   g_col[N_EDGES];
__device__ __align__(16) float g_wv[N_EDGES];
__device__ __align__(16) int   g_part[512];
__device__ __align__(16) float g_bnsum[128];
__device__ __align__(16) float g_bnsq[128];
__device__ __align__(16) float g_bns[128];
__device__ __align__(16) float g_bnt[128];
__device__ __align__(16) float g_bufh[N_NODES * 64];
__device__ __align__(16) float g_bufo[N_NODES * 64];
__device__ __align__(16) float g_bufa[N_NODES * 128];
__device__ __align__(16) __half g_h16 [N_NODES * 64];
__device__ __align__(16) __half g_p016[N_NODES * 64];
__device__ __align__(16) __half g_p116[N_NODES * 64];
__device__ __align__(16) __half g_p216[N_NODES * 64];

// ---------------- helpers ----------------
__device__ __forceinline__ float gelu_f(float v) {
    return 0.5f * v * (1.0f + erff(v * 0.70710678118654752440f));
}

// split float2 into bf16x2 hi + bf16x2 lo (packed .b32)
__device__ __forceinline__ void split2(float2 f, uint32_t& hi, uint32_t& lo) {
    __nv_bfloat162 h = __float22bfloat162_rn(f);
    float2 hf = __bfloat1622float2(h);
    __nv_bfloat162 l = __float22bfloat162_rn(make_float2(f.x - hf.x, f.y - hf.y));
    hi = *(uint32_t*)&h;
    lo = *(uint32_t*)&l;
}

__device__ __forceinline__ void mmabf(float d[4], const uint32_t a[4],
                                      uint32_t b0, uint32_t b1) {
    asm volatile(
        "mma.sync.aligned.m16n8k16.row.col.f32.bf16.bf16.f32 "
        "{%0,%1,%2,%3}, {%4,%5,%6,%7}, {%8,%9}, {%0,%1,%2,%3};"
        : "+f"(d[0]), "+f"(d[1]), "+f"(d[2]), "+f"(d[3])
        : "r"(a[0]), "r"(a[1]), "r"(a[2]), "r"(a[3]), "r"(b0), "r"(b1));
}

// ---------------- preprocessing ----------------
__global__ void detect_k(const int* __restrict__ ei) {
    __shared__ int anynz;
    if (threadIdx.x == 0) anynz = 0;
    __syncthreads();
    if (ei[threadIdx.x * 2 + 1] != 0) anynz = 1;
    __syncthreads();
    if (threadIdx.x == 0) g_is64 = (anynz == 0) ? 1 : 0;
}

__global__ void zero_pre_k() {
    int i = blockIdx.x * blockDim.x + threadIdx.x;
    if (i < N_NODES) g_degi[i] = 0;
    if (i < 128) { g_bnsum[i] = 0.f; g_bnsq[i] = 0.f; }
}

__global__ void convert_k(const void* __restrict__ ei) {
    int e = blockIdx.x * blockDim.x + threadIdx.x;
    if (e >= N_EDGES) return;
    int s, d;
    if (g_is64) {
        const long long* p = (const long long*)ei;
        s = (int)p[e];
        d = (int)p[N_EDGES + e];
    } else {
        const int* p = (const int*)ei;
        s = p[e];
        d = p[N_EDGES + e];
    }
    g_src[e] = s;
    g_dst[e] = d;
    atomicAdd(&g_degi[d], 1);
}

__global__ void dis_k() {
    int i = blockIdx.x * blockDim.x + threadIdx.x;
    if (i >= N_NODES) return;
    int d = g_degi[i];
    g_dis[i] = (d > 0) ? rsqrtf((float)d) : 0.f;
}

// 3-stage scan: block reduce -> scan partials -> block scan
__global__ void blkred_k() {
    __shared__ int ws[8];
    int i = blockIdx.x * 256 + threadIdx.x;
    int v = (i < N_NODES) ? g_degi[i] : 0;
#pragma unroll
    for (int o = 16; o; o >>= 1) v += __shfl_down_sync(0xffffffffu, v, o);
    if ((threadIdx.x & 31) == 0) ws[threadIdx.x >> 5] = v;
    __syncthreads();
    if (threadIdx.x < 8) {
        int t = ws[threadIdx.x];
#pragma unroll
        for (int o = 4; o; o >>= 1) t += __shfl_down_sync(0xffu, t, o);
        if (threadIdx.x == 0) g_part[blockIdx.x] = t;
    }
}

__global__ void partscan_k(int nb) {
    __shared__ int ws[16];
    int t = threadIdx.x, lane = t & 31, w = t >> 5;
    int v = (t < nb) ? g_part[t] : 0;
    int x = v;
#pragma unroll
    for (int o = 1; o < 32; o <<= 1) {
        int y = __shfl_up_sync(0xffffffffu, x, o);
        if (lane >= o) x += y;
    }
    if (lane == 31) ws[w] = x;
    __syncthreads();
    if (w == 0 && lane < 16) {
        int s = ws[lane];
#pragma unroll
        for (int o = 1; o < 16; o <<= 1) {
            int y = __shfl_up_sync(0x0000ffffu, s, o);
            if (lane >= o) s += y;
        }
        ws[lane] = s;
    }
    __syncthreads();
    int pre = (w ? ws[w - 1] : 0) + x - v;
    if (t < nb) g_part[t] = pre;
    if (t == nb - 1) g_rowptr[N_NODES] = pre + v;
}

__global__ void blkscan_k() {
    __shared__ int ws[8];
    int t = threadIdx.x, lane = t & 31, w = t >> 5;
    int i = blockIdx.x * 256 + t;
    int v = (i < N_NODES) ? g_degi[i] : 0;
    int x = v;
#pragma unroll
    for (int o = 1; o < 32; o <<= 1) {
        int y = __shfl_up_sync(0xffffffffu, x, o);
        if (lane >= o) x += y;
    }
    if (lane == 31) ws[w] = x;
    __syncthreads();
    if (w == 0 && lane < 8) {
        int s = ws[lane];
#pragma unroll
        for (int o = 1; o < 8; o <<= 1) {
            int y = __shfl_up_sync(0x000000ffu, s, o);
            if (lane >= o) s += y;
        }
        ws[lane] = s;
    }
    __syncthreads();
    int ex = g_part[blockIdx.x] + (w ? ws[w - 1] : 0) + x - v;
    if (i < N_NODES) { g_rowptr[i] = ex; g_fill[i] = ex; }
}

__global__ void csrfill_k() {
    int e = blockIdx.x * blockDim.x + threadIdx.x;
    if (e >= N_EDGES) return;
    int s = g_src[e], d = g_dst[e];
    int pos = atomicAdd(&g_fill[d], 1);
    g_col[pos] = s;
    g_wv[pos]  = g_dis[s] * g_dis[d];
}

__global__ void bn_stats_k(const float* __restrict__ x) {
    int col = threadIdx.x & 127;
    int r = blockIdx.x * 2 + (threadIdx.x >> 7);
    float s = 0.f, q = 0.f;
    for (; r < N_NODES; r += gridDim.x * 2) {
        float v = x[(size_t)r * 128 + col];
        s += v;
        q += v * v;
    }
    atomicAdd(&g_bnsum[col], s);
    atomicAdd(&g_bnsq[col], q);
}

__global__ void bn_final_k(const float* __restrict__ gamma, const float* __restrict__ beta) {
    int c = threadIdx.x;
    float mean = g_bnsum[c] * (1.0f / N_NODES);
    float var  = g_bnsq[c] * (1.0f / N_NODES) - mean * mean;
    float s = gamma[c] * rsqrtf(var + 1e-5f);
    g_bns[c] = s;
    g_bnt[c] = beta[c] - mean * s;
}

// CSR propagation, fp16 features (64 per node = 32 half2), warp per node.
__global__ void __launch_bounds__(256) prop_k(const __half2* __restrict__ in,
                                              __half2* __restrict__ out) {
    int node = (blockIdx.x << 3) + (threadIdx.x >> 5);
    int lane = threadIdx.x & 31;
    int beg = g_rowptr[node], end = g_rowptr[node + 1];
    float ax = 0.f, ay = 0.f;
    int e = beg;
    for (; e + 1 < end; e += 2) {
        int s0 = g_col[e], s1 = g_col[e + 1];
        float w0 = g_wv[e], w1 = g_wv[e + 1];
        float2 f0 = __half22float2(__ldg(in + (size_t)s0 * 32 + lane));
        float2 f1 = __half22float2(__ldg(in + (size_t)s1 * 32 + lane));
        ax = fmaf(w0, f0.x, fmaf(w1, f1.x, ax));
        ay = fmaf(w0, f0.y, fmaf(w1, f1.y, ay));
    }
    if (e < end) {
        int s0 = g_col[e];
        float w0 = g_wv[e];
        float2 f0 = __half22float2(__ldg(in + (size_t)s0 * 32 + lane));
        ax = fmaf(w0, f0.x, ax);
        ay = fmaf(w0, f0.y, ay);
    }
    out[(size_t)node * 32 + lane] = __float22half2_rn(make_float2(ax, ay));
}

// ---------------- bf16 2-way-split tensor-core GEMM ----------------
// C[N_NODES, NOUT] = act( concat_segs(A)[N_NODES, KD] @ W[KD, NOUT] + bias )
// Segments may be fp32 or fp16 (fp16mask bit per segment). 128 rows/block,
// 8 warps (4m x 2n), warp tile 32 x NOUT/2. mma.m16n8k16.bf16, hi/lo split.
template <int KD, int NOUT, bool ACT, bool BNA, bool DUAL>
__global__ void __launch_bounds__(256) tgemm_k(
    const void* __restrict__ p0_, const void* __restrict__ p1_,
    const void* __restrict__ p2_, const void* __restrict__ p3_,
    int w0, int w1, int w2, int fp16mask,
    const float* __restrict__ W, const float* __restrict__ bias,
    float* __restrict__ C, __half* __restrict__ C16) {
    __shared__ float As[128][36];
    __shared__ __nv_bfloat16 Wh[NOUT][36];
    __shared__ __nv_bfloat16 Wl[NOUT][36];

    constexpr int NT = NOUT / 16;
    int tid = threadIdx.x;
    int lane = tid & 31, wid = tid >> 5;
    int gid = lane >> 2, tg = lane & 3;
    int warp_m = wid & 3, warp_n = wid >> 2;
    int Rm = warp_m * 32;
    int Cn = warp_n * (NOUT / 2);
    int m0 = blockIdx.x * 128;

    float d[2][NT][4];
#pragma unroll
    for (int mt = 0; mt < 2; mt++)
#pragma unroll
        for (int nt = 0; nt < NT; nt++)
#pragma unroll
            for (int q = 0; q < 4; q++) d[mt][nt][q] = 0.f;

    for (int k0 = 0; k0 < KD; k0 += 32) {
        // segment select
        const void* Ap = p0_; int Aw = w0, cum = 0, seg = 0;
        if (k0 >= w0)           { Ap = p1_; Aw = w1; cum = w0; seg = 1; }
        if (k0 >= w0 + w1)      { Ap = p2_; Aw = w2; cum = w0 + w1; seg = 2; }
        if (k0 >= w0 + w1 + w2) { Ap = p3_; Aw = KD - w0 - w1 - w2; cum = w0 + w1 + w2; seg = 3; }
        int kloc = k0 - cum;
        bool is16 = (fp16mask >> seg) & 1;

        // 128x32 A tile
#pragma unroll
        for (int pass = 0; pass < 4; pass++) {
            int r  = pass * 32 + (tid >> 3);
            int c4 = (tid & 7) * 4;
            int gr = m0 + r;
            float4 v = make_float4(0.f, 0.f, 0.f, 0.f);
            if (gr < N_NODES) {
                if (is16) {
                    const __half2* hp = (const __half2*)Ap;
                    size_t base = ((size_t)gr * Aw + kloc + c4) >> 1;
                    float2 fa = __half22float2(hp[base]);
                    float2 fb = __half22float2(hp[base + 1]);
                    v = make_float4(fa.x, fa.y, fb.x, fb.y);
                } else {
                    v = *(const float4*)((const float*)Ap + (size_t)gr * Aw + kloc + c4);
                }
            }
            if (BNA) {
                int kc = k0 + c4;
                v.x = v.x * g_bns[kc]     + g_bnt[kc];
                v.y = v.y * g_bns[kc + 1] + g_bnt[kc + 1];
                v.z = v.z * g_bns[kc + 2] + g_bnt[kc + 2];
                v.w = v.w * g_bns[kc + 3] + g_bnt[kc + 3];
            }
            *(float4*)&As[r][c4] = v;
        }
        // 32xNOUT W tile -> transposed bf16 hi/lo
        for (int idx = tid; idx < 32 * NOUT / 4; idx += 256) {
            int kr = idx / (NOUT / 4);
            int c4 = (idx % (NOUT / 4)) * 4;
            float4 wv = *(const float4*)(W + (size_t)(k0 + kr) * NOUT + c4);
            float wf[4] = {wv.x, wv.y, wv.z, wv.w};
#pragma unroll
            for (int q = 0; q < 4; q++) {
                __nv_bfloat16 h = __float2bfloat16_rn(wf[q]);
                float hf = __bfloat162float(h);
                Wh[c4 + q][kr] = h;
                Wl[c4 + q][kr] = __float2bfloat16_rn(wf[q] - hf);
            }
        }
        __syncthreads();

#pragma unroll
        for (int ks = 0; ks < 2; ks++) {
            int kk = ks * 16;
            uint32_t ah[2][4], al[2][4];
#pragma unroll
            for (int mt = 0; mt < 2; mt++) {
                int r0 = Rm + mt * 16 + gid;
                float2 f0 = *(float2*)&As[r0][kk + 2 * tg];
                float2 f1 = *(float2*)&As[r0 + 8][kk + 2 * tg];
                float2 f2 = *(float2*)&As[r0][kk + 8 + 2 * tg];
                float2 f3 = *(float2*)&As[r0 + 8][kk + 8 + 2 * tg];
                split2(f0, ah[mt][0], al[mt][0]);
                split2(f1, ah[mt][1], al[mt][1]);
                split2(f2, ah[mt][2], al[mt][2]);
                split2(f3, ah[mt][3], al[mt][3]);
            }
#pragma unroll
            for (int nt = 0; nt < NT; nt++) {
                int col = Cn + nt * 8 + gid;
                uint32_t bh0 = *(uint32_t*)&Wh[col][kk + 2 * tg];
                uint32_t bh1 = *(uint32_t*)&Wh[col][kk + 8 + 2 * tg];
                uint32_t bl0 = *(uint32_t*)&Wl[col][kk + 2 * tg];
                uint32_t bl1 = *(uint32_t*)&Wl[col][kk + 8 + 2 * tg];
#pragma unroll
                for (int mt = 0; mt < 2; mt++) {
                    mmabf(d[mt][nt], ah[mt], bh0, bh1);
                    mmabf(d[mt][nt], al[mt], bh0, bh1);
                    mmabf(d[mt][nt], ah[mt], bl0, bl1);
                }
            }
        }
        __syncthreads();
    }

    // epilogue
#pragma unroll
    for (int mt = 0; mt < 2; mt++) {
#pragma unroll
        for (int nt = 0; nt < NT; nt++) {
            int col = Cn + nt * 8 + tg * 2;
            float bx = bias[col], by = bias[col + 1];
            int r0 = m0 + Rm + mt * 16 + gid;
            int r1 = r0 + 8;
            float v0 = d[mt][nt][0] + bx, v1 = d[mt][nt][1] + by;
            float v2 = d[mt][nt][2] + bx, v3 = d[mt][nt][3] + by;
            if (ACT) { v0 = gelu_f(v0); v1 = gelu_f(v1); v2 = gelu_f(v2); v3 = gelu_f(v3); }
            if (r0 < N_NODES) {
                *(float2*)(C + (size_t)r0 * NOUT + col) = make_float2(v0, v1);
                if (DUAL) *(__half2*)(C16 + (size_t)r0 * NOUT + col) =
                    __float22half2_rn(make_float2(v0, v1));
            }
            if (r1 < N_NODES) {
                *(float2*)(C + (size_t)r1 * NOUT + col) = make_float2(v2, v3);
                if (DUAL) *(__half2*)(C16 + (size_t)r1 * NOUT + col) =
                    __float22half2_rn(make_float2(v2, v3));
            }
        }
    }
}

// ---------------- host launcher ----------------
extern "C" void kernel_launch(void* const* d_in, const int* in_sizes, int n_in,
                              void* d_out, int out_size) {
    const float* x     = (const float*)d_in[0];
    const void*  ei    = d_in[1];
    const float* gamma = (const float*)d_in[2];
    const float* beta  = (const float*)d_in[3];
    const float* W1 = (const float*)d_in[4];  const float* b1  = (const float*)d_in[5];
    const float* T1 = (const float*)d_in[6];  const float* t1b = (const float*)d_in[7];
    const float* W2 = (const float*)d_in[8];  const float* b2  = (const float*)d_in[9];
    const float* T2 = (const float*)d_in[10]; const float* t2b = (const float*)d_in[11];
    const float* W3 = (const float*)d_in[12]; const float* b3  = (const float*)d_in[13];
    const float* W4 = (const float*)d_in[14]; const float* b4  = (const float*)d_in[15];
    float* out = (float*)d_out;

    float *bufh, *bufo, *bufa;
    __half *h16, *p016, *p116, *p216;
    cudaGetSymbolAddress((void**)&bufh, g_bufh);
    cudaGetSymbolAddress((void**)&bufo, g_bufo);
    cudaGetSymbolAddress((void**)&bufa, g_bufa);
    cudaGetSymbolAddress((void**)&h16,  g_h16);
    cudaGetSymbolAddress((void**)&p016, g_p016);
    cudaGetSymbolAddress((void**)&p116, g_p116);
    cudaGetSymbolAddress((void**)&p216, g_p216);

    const int EB = (N_EDGES + 255) / 256;
    const int NB = (N_NODES + 255) / 256;   // 391
    const int GB = (N_NODES + 127) / 128;   // 782
    const int PB = N_NODES / 8;             // 12500

    // ---- graph preprocessing + BN stats ----
    detect_k<<<1, 256>>>((const int*)ei);
    zero_pre_k<<<NB, 256>>>();
    convert_k<<<EB, 256>>>(ei);
    dis_k<<<NB, 256>>>();
    blkred_k<<<NB, 256>>>();
    partscan_k<<<1, 512>>>(NB);
    blkscan_k<<<NB, 256>>>();
    csrfill_k<<<EB, 256>>>();
    bn_stats_k<<<512, 256>>>(x);
    bn_final_k<<<1, 128>>>(gamma, beta);

    // ---- layer 1: h = gelu(BN(x) @ W1 + b1), dual fp32+fp16 output ----
    tgemm_k<128, 64, true, true, true><<<GB, 256>>>(
        x, x, x, x, 128, 0, 0, 0, W1, b1, bufh, h16);

    // ---- TAGConv 1: 3 fp16 props + ONE fused K=256 GEMM ----
    prop_k<<<PB, 256>>>((const __half2*)h16,  (__half2*)p016);
    prop_k<<<PB, 256>>>((const __half2*)p016, (__half2*)p116);
    prop_k<<<PB, 256>>>((const __half2*)p116, (__half2*)p216);
    tgemm_k<256, 64, true, false, false><<<GB, 256>>>(
        bufh, p016, p116, p216, 64, 64, 64, 0b1110, T1, t1b, bufo, nullptr);

    // ---- layer 2 ----
    tgemm_k<64, 64, true, false, true><<<GB, 256>>>(
        bufo, bufo, bufo, bufo, 64, 0, 0, 0, W2, b2, bufh, h16);

    // ---- TAGConv 2 ----
    prop_k<<<PB, 256>>>((const __half2*)h16,  (__half2*)p016);
    prop_k<<<PB, 256>>>((const __half2*)p016, (__half2*)p116);
    prop_k<<<PB, 256>>>((const __half2*)p116, (__half2*)p216);
    tgemm_k<256, 64, true, false, false><<<GB, 256>>>(
        bufh, p016, p116, p216, 64, 64, 64, 0b1110, T2, t2b, bufo, nullptr);

    // ---- layer 3: a = gelu(concat(x, h) @ W3 + b3) ----
    tgemm_k<192, 128, true, false, false><<<GB, 256>>>(
        x, bufo, bufo, bufo, 128, 64, 0, 0, W3, b3, bufa, nullptr);

    // ---- layer 4: out = a @ W4 + b4 ----
    tgemm_k<128, 64, false, false, false><<<GB, 256>>>(
        bufa, bufa, bufa, bufa, 128, 0, 0, 0, W4, b4, out, nullptr);
}

// round 4
// speedup vs baseline: 1.8368x; 1.0152x over previous
#include <cuda_runtime.h>
#include <cuda_fp16.h>
#include <cuda_bf16.h>
#include <math.h>
#include <stdint.h>

#define N_NODES 100000
#define N_EDGES 1000000

// ---------------- device scratch ----------------
__device__ int   g_is64;
__device__ __align__(16) int   g_src[N_EDGES];
__device__ __align__(16) int   g_dst[N_EDGES];
__device__ __align__(16) int   g_degi[N_NODES];
__device__ __align__(16) float g_dis[N_NODES];
__device__ __align__(16) int   g_rowptr[N_NODES + 1];
__device__ __align__(16) int   g_fill[N_NODES];
__device__ __align__(16) int   g_col[N_EDGES];
__device__ __align__(16) float g_wv[N_EDGES];
__device__ __align__(16) int   g_part[512];
__device__ __align__(16) float g_bnsum[128];
__device__ __align__(16) float g_bnsq[128];
__device__ __align__(16) float g_bns[128];
__device__ __align__(16) float g_bnt[128];
__device__ __align__(16) float g_bufh[N_NODES * 64];
__device__ __align__(16) __half g_a16 [N_NODES * 128];
__device__ __align__(16) __half g_h16 [N_NODES * 64];
__device__ __align__(16) __half g_p016[N_NODES * 64];
__device__ __align__(16) __half g_p116[N_NODES * 64];
__device__ __align__(16) __half g_p216[N_NODES * 64];

// ---------------- helpers ----------------
__device__ __forceinline__ float gelu_f(float v) {
    return 0.5f * v * (1.0f + erff(v * 0.70710678118654752440f));
}

__device__ __forceinline__ void split2(float2 f, uint32_t& hi, uint32_t& lo) {
    __nv_bfloat162 h = __float22bfloat162_rn(f);
    float2 hf = __bfloat1622float2(h);
    __nv_bfloat162 l = __float22bfloat162_rn(make_float2(f.x - hf.x, f.y - hf.y));
    hi = *(uint32_t*)&h;
    lo = *(uint32_t*)&l;
}

__device__ __forceinline__ void mmabf(float d[4], const uint32_t a[4],
                                      uint32_t b0, uint32_t b1) {
    asm volatile(
        "mma.sync.aligned.m16n8k16.row.col.f32.bf16.bf16.f32 "
        "{%0,%1,%2,%3}, {%4,%5,%6,%7}, {%8,%9}, {%0,%1,%2,%3};"
        : "+f"(d[0]), "+f"(d[1]), "+f"(d[2]), "+f"(d[3])
        : "r"(a[0]), "r"(a[1]), "r"(a[2]), "r"(a[3]), "r"(b0), "r"(b1));
}

// segmented A-tile fill: 128 rows x 32 cols into As, fp32/fp16 segments
template <bool BNA>
__device__ __forceinline__ void fill_A_seg(
    float (*As)[36], int m0, int k0,
    const void* p0_, const void* p1_, const void* p2_, const void* p3_,
    int w0, int w1, int w2, int KD, int fp16mask, int tid) {
    const void* Ap = p0_; int Aw = w0, cum = 0, seg = 0;
    if (k0 >= w0)           { Ap = p1_; Aw = w1; cum = w0; seg = 1; }
    if (k0 >= w0 + w1)      { Ap = p2_; Aw = w2; cum = w0 + w1; seg = 2; }
    if (k0 >= w0 + w1 + w2) { Ap = p3_; Aw = KD - w0 - w1 - w2; cum = w0 + w1 + w2; seg = 3; }
    int kloc = k0 - cum;
    bool is16 = (fp16mask >> seg) & 1;
#pragma unroll
    for (int pass = 0; pass < 4; pass++) {
        int r  = pass * 32 + (tid >> 3);
        int c4 = (tid & 7) * 4;
        int gr = m0 + r;
        float4 v = make_float4(0.f, 0.f, 0.f, 0.f);
        if (gr < N_NODES) {
            if (is16) {
                const __half2* hp = (const __half2*)Ap;
                size_t base = ((size_t)gr * Aw + kloc + c4) >> 1;
                float2 fa = __half22float2(hp[base]);
                float2 fb = __half22float2(hp[base + 1]);
                v = make_float4(fa.x, fa.y, fb.x, fb.y);
            } else {
                v = *(const float4*)((const float*)Ap + (size_t)gr * Aw + kloc + c4);
            }
        }
        if (BNA) {
            int kc = k0 + c4;
            v.x = v.x * g_bns[kc]     + g_bnt[kc];
            v.y = v.y * g_bns[kc + 1] + g_bnt[kc + 1];
            v.z = v.z * g_bns[kc + 2] + g_bnt[kc + 2];
            v.w = v.w * g_bns[kc + 3] + g_bnt[kc + 3];
        }
        *(float4*)&As[r][c4] = v;
    }
}

// W tile fill: 32 x NOUT fp32 -> transposed bf16 hi/lo
__device__ __forceinline__ void fill_W(
    __nv_bfloat16 (*Wh)[36], __nv_bfloat16 (*Wl)[36],
    const float* __restrict__ W, int k0, int NOUT, int tid) {
    for (int idx = tid; idx < 32 * NOUT / 4; idx += 256) {
        int kr = idx / (NOUT / 4);
        int c4 = (idx % (NOUT / 4)) * 4;
        float4 wv = *(const float4*)(W + (size_t)(k0 + kr) * NOUT + c4);
        float wf[4] = {wv.x, wv.y, wv.z, wv.w};
#pragma unroll
        for (int q = 0; q < 4; q++) {
            __nv_bfloat16 h = __float2bfloat16_rn(wf[q]);
            Wh[c4 + q][kr] = h;
            Wl[c4 + q][kr] = __float2bfloat16_rn(wf[q] - __bfloat162float(h));
        }
    }
}

// one 32-K step of split-bf16 mma from a float buffer (stride astr)
template <int NT>
__device__ __forceinline__ void mma_tile(
    float d[2][NT][4], const float* Ab, int astr,
    __nv_bfloat16 (*Wh)[36], __nv_bfloat16 (*Wl)[36],
    int Rm, int Cn, int gid, int tg) {
#pragma unroll
    for (int ks = 0; ks < 2; ks++) {
        int kk = ks * 16;
        uint32_t ah[2][4], al[2][4];
#pragma unroll
        for (int mt = 0; mt < 2; mt++) {
            const float* ap = Ab + (size_t)(Rm + mt * 16 + gid) * astr + kk + 2 * tg;
            float2 f0 = *(const float2*)ap;
            float2 f1 = *(const float2*)(ap + 8 * astr);
            float2 f2 = *(const float2*)(ap + 8);
            float2 f3 = *(const float2*)(ap + 8 * astr + 8);
            split2(f0, ah[mt][0], al[mt][0]);
            split2(f1, ah[mt][1], al[mt][1]);
            split2(f2, ah[mt][2], al[mt][2]);
            split2(f3, ah[mt][3], al[mt][3]);
        }
#pragma unroll
        for (int nt = 0; nt < NT; nt++) {
            int col = Cn + nt * 8 + gid;
            uint32_t bh0 = *(uint32_t*)&Wh[col][kk + 2 * tg];
            uint32_t bh1 = *(uint32_t*)&Wh[col][kk + 8 + 2 * tg];
            uint32_t bl0 = *(uint32_t*)&Wl[col][kk + 2 * tg];
            uint32_t bl1 = *(uint32_t*)&Wl[col][kk + 8 + 2 * tg];
#pragma unroll
            for (int mt = 0; mt < 2; mt++) {
                mmabf(d[mt][nt], ah[mt], bh0, bh1);
                mmabf(d[mt][nt], al[mt], bh0, bh1);
                mmabf(d[mt][nt], ah[mt], bl0, bl1);
            }
        }
    }
}

// ---------------- preprocessing ----------------
__global__ void detect_k(const int* __restrict__ ei) {
    __shared__ int anynz;
    if (threadIdx.x == 0) anynz = 0;
    __syncthreads();
    if (ei[threadIdx.x * 2 + 1] != 0) anynz = 1;
    __syncthreads();
    if (threadIdx.x == 0) g_is64 = (anynz == 0) ? 1 : 0;
}

__global__ void zero_pre_k() {
    int i = blockIdx.x * blockDim.x + threadIdx.x;
    if (i < N_NODES) g_degi[i] = 0;
    if (i < 128) { g_bnsum[i] = 0.f; g_bnsq[i] = 0.f; }
}

__global__ void convert_k(const void* __restrict__ ei) {
    int e = blockIdx.x * blockDim.x + threadIdx.x;
    if (e >= N_EDGES) return;
    int s, d;
    if (g_is64) {
        const long long* p = (const long long*)ei;
        s = (int)p[e];
        d = (int)p[N_EDGES + e];
    } else {
        const int* p = (const int*)ei;
        s = p[e];
        d = p[N_EDGES + e];
    }
    g_src[e] = s;
    g_dst[e] = d;
    atomicAdd(&g_degi[d], 1);
}

__global__ void dis_k() {
    int i = blockIdx.x * blockDim.x + threadIdx.x;
    if (i >= N_NODES) return;
    int d = g_degi[i];
    g_dis[i] = (d > 0) ? rsqrtf((float)d) : 0.f;
}

__global__ void blkred_k() {
    __shared__ int ws[8];
    int i = blockIdx.x * 256 + threadIdx.x;
    int v = (i < N_NODES) ? g_degi[i] : 0;
#pragma unroll
    for (int o = 16; o; o >>= 1) v += __shfl_down_sync(0xffffffffu, v, o);
    if ((threadIdx.x & 31) == 0) ws[threadIdx.x >> 5] = v;
    __syncthreads();
    if (threadIdx.x < 8) {
        int t = ws[threadIdx.x];
#pragma unroll
        for (int o = 4; o; o >>= 1) t += __shfl_down_sync(0xffu, t, o);
        if (threadIdx.x == 0) g_part[blockIdx.x] = t;
    }
}

__global__ void partscan_k(int nb) {
    __shared__ int ws[16];
    int t = threadIdx.x, lane = t & 31, w = t >> 5;
    int v = (t < nb) ? g_part[t] : 0;
    int x = v;
#pragma unroll
    for (int o = 1; o < 32; o <<= 1) {
        int y = __shfl_up_sync(0xffffffffu, x, o);
        if (lane >= o) x += y;
    }
    if (lane == 31) ws[w] = x;
    __syncthreads();
    if (w == 0 && lane < 16) {
        int s = ws[lane];
#pragma unroll
        for (int o = 1; o < 16; o <<= 1) {
            int y = __shfl_up_sync(0x0000ffffu, s, o);
            if (lane >= o) s += y;
        }
        ws[lane] = s;
    }
    __syncthreads();
    int pre = (w ? ws[w - 1] : 0) + x - v;
    if (t < nb) g_part[t] = pre;
    if (t == nb - 1) g_rowptr[N_NODES] = pre + v;
}

__global__ void blkscan_k() {
    __shared__ int ws[8];
    int t = threadIdx.x, lane = t & 31, w = t >> 5;
    int i = blockIdx.x * 256 + t;
    int v = (i < N_NODES) ? g_degi[i] : 0;
    int x = v;
#pragma unroll
    for (int o = 1; o < 32; o <<= 1) {
        int y = __shfl_up_sync(0xffffffffu, x, o);
        if (lane >= o) x += y;
    }
    if (lane == 31) ws[w] = x;
    __syncthreads();
    if (w == 0 && lane < 8) {
        int s = ws[lane];
#pragma unroll
        for (int o = 1; o < 8; o <<= 1) {
            int y = __shfl_up_sync(0x000000ffu, s, o);
            if (lane >= o) s += y;
        }
        ws[lane] = s;
    }
    __syncthreads();
    int ex = g_part[blockIdx.x] + (w ? ws[w - 1] : 0) + x - v;
    if (i < N_NODES) { g_rowptr[i] = ex; g_fill[i] = ex; }
}

__global__ void csrfill_k() {
    int e = blockIdx.x * blockDim.x + threadIdx.x;
    if (e >= N_EDGES) return;
    int s = g_src[e], d = g_dst[e];
    int pos = atomicAdd(&g_fill[d], 1);
    g_col[pos] = s;
    g_wv[pos]  = g_dis[s] * g_dis[d];
}

__global__ void bn_stats_k(const float* __restrict__ x) {
    int col = threadIdx.x & 127;
    int r = blockIdx.x * 2 + (threadIdx.x >> 7);
    float s = 0.f, q = 0.f;
    for (; r < N_NODES; r += gridDim.x * 2) {
        float v = x[(size_t)r * 128 + col];
        s += v;
        q += v * v;
    }
    atomicAdd(&g_bnsum[col], s);
    atomicAdd(&g_bnsq[col], q);
}

__global__ void bn_final_k(const float* __restrict__ gamma, const float* __restrict__ beta) {
    int c = threadIdx.x;
    float mean = g_bnsum[c] * (1.0f / N_NODES);
    float var  = g_bnsq[c] * (1.0f / N_NODES) - mean * mean;
    float s = gamma[c] * rsqrtf(var + 1e-5f);
    g_bns[c] = s;
    g_bnt[c] = beta[c] - mean * s;
}

// CSR propagation, fp16 feats, warp per node, unroll 4 for MLP
__global__ void __launch_bounds__(256) prop_k(const __half2* __restrict__ in,
                                              __half2* __restrict__ out) {
    int node = (blockIdx.x << 3) + (threadIdx.x >> 5);
    int lane = threadIdx.x & 31;
    int beg = g_rowptr[node], end = g_rowptr[node + 1];
    float ax = 0.f, ay = 0.f;
    int e = beg;
    for (; e + 3 < end; e += 4) {
        int s0 = g_col[e], s1 = g_col[e + 1], s2 = g_col[e + 2], s3 = g_col[e + 3];
        float w0 = g_wv[e], w1 = g_wv[e + 1], w2 = g_wv[e + 2], w3 = g_wv[e + 3];
        float2 f0 = __half22float2(__ldg(in + (size_t)s0 * 32 + lane));
        float2 f1 = __half22float2(__ldg(in + (size_t)s1 * 32 + lane));
        float2 f2 = __half22float2(__ldg(in + (size_t)s2 * 32 + lane));
        float2 f3 = __half22float2(__ldg(in + (size_t)s3 * 32 + lane));
        ax = fmaf(w0, f0.x, fmaf(w1, f1.x, fmaf(w2, f2.x, fmaf(w3, f3.x, ax))));
        ay = fmaf(w0, f0.y, fmaf(w1, f1.y, fmaf(w2, f2.y, fmaf(w3, f3.y, ay))));
    }
    for (; e < end; e++) {
        int s0 = g_col[e];
        float w0 = g_wv[e];
        float2 f0 = __half22float2(__ldg(in + (size_t)s0 * 32 + lane));
        ax = fmaf(w0, f0.x, ax);
        ay = fmaf(w0, f0.y, ay);
    }
    out[(size_t)node * 32 + lane] = __float22half2_rn(make_float2(ax, ay));
}

// ---------------- standalone GEMM (L1, L4) ----------------
template <int KD, int NOUT, bool ACT, bool BNA, bool DUAL>
__global__ void __launch_bounds__(256) tgemm_k(
    const void* __restrict__ p0_, const void* __restrict__ p1_,
    const void* __restrict__ p2_, const void* __restrict__ p3_,
    int w0, int w1, int w2, int fp16mask,
    const float* __restrict__ W, const float* __restrict__ bias,
    float* __restrict__ C, __half* __restrict__ C16) {
    __shared__ float As[128][36];
    __shared__ __nv_bfloat16 Wh[NOUT][36];
    __shared__ __nv_bfloat16 Wl[NOUT][36];

    constexpr int NT = NOUT / 16;
    int tid = threadIdx.x;
    int lane = tid & 31, wid = tid >> 5;
    int gid = lane >> 2, tg = lane & 3;
    int warp_m = wid & 3, warp_n = wid >> 2;
    int Rm = warp_m * 32;
    int Cn = warp_n * (NOUT / 2);
    int m0 = blockIdx.x * 128;

    float d[2][NT][4];
#pragma unroll
    for (int mt = 0; mt < 2; mt++)
#pragma unroll
        for (int nt = 0; nt < NT; nt++)
#pragma unroll
            for (int q = 0; q < 4; q++) d[mt][nt][q] = 0.f;

    for (int k0 = 0; k0 < KD; k0 += 32) {
        fill_A_seg<BNA>(As, m0, k0, p0_, p1_, p2_, p3_, w0, w1, w2, KD, fp16mask, tid);
        fill_W(Wh, Wl, W, k0, NOUT, tid);
        __syncthreads();
        mma_tile<NT>(d, &As[0][0], 36, Wh, Wl, Rm, Cn, gid, tg);
        __syncthreads();
    }

#pragma unroll
    for (int mt = 0; mt < 2; mt++) {
#pragma unroll
        for (int nt = 0; nt < NT; nt++) {
            int col = Cn + nt * 8 + tg * 2;
            float bx = bias[col], by = bias[col + 1];
            int r0 = m0 + Rm + mt * 16 + gid;
            int r1 = r0 + 8;
            float v0 = d[mt][nt][0] + bx, v1 = d[mt][nt][1] + by;
            float v2 = d[mt][nt][2] + bx, v3 = d[mt][nt][3] + by;
            if (ACT) { v0 = gelu_f(v0); v1 = gelu_f(v1); v2 = gelu_f(v2); v3 = gelu_f(v3); }
            if (r0 < N_NODES) {
                *(float2*)(C + (size_t)r0 * NOUT + col) = make_float2(v0, v1);
                if (DUAL) *(__half2*)(C16 + (size_t)r0 * NOUT + col) =
                    __float22half2_rn(make_float2(v0, v1));
            }
            if (r1 < N_NODES) {
                *(float2*)(C + (size_t)r1 * NOUT + col) = make_float2(v2, v3);
                if (DUAL) *(__half2*)(C16 + (size_t)r1 * NOUT + col) =
                    __float22half2_rn(make_float2(v2, v3));
            }
        }
    }
}

// ---------------- fused 2-stage chain GEMM ----------------
// stage1: Cs = gelu(segs[K1] @ Wa + ba)   (N1 = 64, kept in smem)
// stage2: out = gelu(concat(xg[XW], Cs) @ Wb + bb)   (N2, to global fp32/fp16)
template <int K1, int XW, int N2, bool W32, bool W16>
__global__ void __launch_bounds__(256) chain_k(
    const void* __restrict__ p0_, const void* __restrict__ p1_,
    const void* __restrict__ p2_, const void* __restrict__ p3_,
    int w0, int w1, int w2, int fp16mask,
    const float* __restrict__ Wa, const float* __restrict__ ba,
    const float* __restrict__ xg,
    const float* __restrict__ Wb, const float* __restrict__ bb,
    float* __restrict__ C, __half* __restrict__ C16) {
    constexpr int NW = (N2 > 64) ? N2 : 64;
    extern __shared__ char sm[];
    float (*As)[36] = (float(*)[36])(sm);                                  // 18432 B
    float (*Cs)[68] = (float(*)[68])(sm + 18432);                          // 34816 B
    __nv_bfloat16 (*Wh)[36] = (__nv_bfloat16(*)[36])(sm + 53248);
    __nv_bfloat16 (*Wl)[36] = (__nv_bfloat16(*)[36])(sm + 53248 + NW * 72);

    int tid = threadIdx.x;
    int lane = tid & 31, wid = tid >> 5;
    int gid = lane >> 2, tg = lane & 3;
    int warp_m = wid & 3, warp_n = wid >> 2;
    int Rm = warp_m * 32;
    int m0 = blockIdx.x * 128;

    // -------- stage 1 --------
    {
        int Cn = warp_n * 32;
        float d[2][4][4];
#pragma unroll
        for (int mt = 0; mt < 2; mt++)
#pragma unroll
            for (int nt = 0; nt < 4; nt++)
#pragma unroll
                for (int q = 0; q < 4; q++) d[mt][nt][q] = 0.f;

        for (int k0 = 0; k0 < K1; k0 += 32) {
            fill_A_seg<false>(As, m0, k0, p0_, p1_, p2_, p3_, w0, w1, w2, K1, fp16mask, tid);
            fill_W(Wh, Wl, Wa, k0, 64, tid);
            __syncthreads();
            mma_tile<4>(d, &As[0][0], 36, Wh, Wl, Rm, Cn, gid, tg);
            __syncthreads();
        }
#pragma unroll
        for (int mt = 0; mt < 2; mt++) {
#pragma unroll
            for (int nt = 0; nt < 4; nt++) {
                int col = Cn + nt * 8 + tg * 2;
                float bx = ba[col], by = ba[col + 1];
                int r0 = Rm + mt * 16 + gid;
                Cs[r0][col]     = gelu_f(d[mt][nt][0] + bx);
                Cs[r0][col + 1] = gelu_f(d[mt][nt][1] + by);
                Cs[r0 + 8][col]     = gelu_f(d[mt][nt][2] + bx);
                Cs[r0 + 8][col + 1] = gelu_f(d[mt][nt][3] + by);
            }
        }
    }
    __syncthreads();

    // -------- stage 2 --------
    {
        constexpr int NT = N2 / 16;
        int Cn = warp_n * (N2 / 2);
        float d[2][NT][4];
#pragma unroll
        for (int mt = 0; mt < 2; mt++)
#pragma unroll
            for (int nt = 0; nt < NT; nt++)
#pragma unroll
                for (int q = 0; q < 4; q++) d[mt][nt][q] = 0.f;

        for (int k0 = 0; k0 < XW + 64; k0 += 32) {
            bool from_x = (XW > 0) && (k0 < XW);
            if (from_x) {
#pragma unroll
                for (int pass = 0; pass < 4; pass++) {
                    int r  = pass * 32 + (tid >> 3);
                    int c4 = (tid & 7) * 4;
                    int gr = m0 + r;
                    float4 v = make_float4(0.f, 0.f, 0.f, 0.f);
                    if (gr < N_NODES)
                        v = *(const float4*)(xg + (size_t)gr * XW + k0 + c4);
                    *(float4*)&As[r][c4] = v;
                }
            }
            fill_W(Wh, Wl, Wb, k0, N2, tid);
            __syncthreads();
            const float* Ab = from_x ? &As[0][0] : &Cs[0][k0 - XW];
            int astr = from_x ? 36 : 68;
            mma_tile<NT>(d, Ab, astr, Wh, Wl, Rm, Cn, gid, tg);
            __syncthreads();
        }

#pragma unroll
        for (int mt = 0; mt < 2; mt++) {
#pragma unroll
            for (int nt = 0; nt < NT; nt++) {
                int col = Cn + nt * 8 + tg * 2;
                float bx = bb[col], by = bb[col + 1];
                int r0 = m0 + Rm + mt * 16 + gid;
                int r1 = r0 + 8;
                float v0 = gelu_f(d[mt][nt][0] + bx), v1 = gelu_f(d[mt][nt][1] + by);
                float v2 = gelu_f(d[mt][nt][2] + bx), v3 = gelu_f(d[mt][nt][3] + by);
                if (r0 < N_NODES) {
                    if (W32) *(float2*)(C + (size_t)r0 * N2 + col) = make_float2(v0, v1);
                    if (W16) *(__half2*)(C16 + (size_t)r0 * N2 + col) =
                        __float22half2_rn(make_float2(v0, v1));
                }
                if (r1 < N_NODES) {
                    if (W32) *(float2*)(C + (size_t)r1 * N2 + col) = make_float2(v2, v3);
                    if (W16) *(__half2*)(C16 + (size_t)r1 * N2 + col) =
                        __float22half2_rn(make_float2(v2, v3));
                }
            }
        }
    }
}

// ---------------- host launcher ----------------
extern "C" void kernel_launch(void* const* d_in, const int* in_sizes, int n_in,
                              void* d_out, int out_size) {
    const float* x     = (const float*)d_in[0];
    const void*  ei    = d_in[1];
    const float* gamma = (const float*)d_in[2];
    const float* beta  = (const float*)d_in[3];
    const float* W1 = (const float*)d_in[4];  const float* b1  = (const float*)d_in[5];
    const float* T1 = (const float*)d_in[6];  const float* t1b = (const float*)d_in[7];
    const float* W2 = (const float*)d_in[8];  const float* b2  = (const float*)d_in[9];
    const float* T2 = (const float*)d_in[10]; const float* t2b = (const float*)d_in[11];
    const float* W3 = (const float*)d_in[12]; const float* b3  = (const float*)d_in[13];
    const float* W4 = (const float*)d_in[14]; const float* b4  = (const float*)d_in[15];
    float* out = (float*)d_out;

    float *bufh;
    __half *h16, *p016, *p116, *p216, *a16;
    cudaGetSymbolAddress((void**)&bufh, g_bufh);
    cudaGetSymbolAddress((void**)&h16,  g_h16);
    cudaGetSymbolAddress((void**)&p016, g_p016);
    cudaGetSymbolAddress((void**)&p116, g_p116);
    cudaGetSymbolAddress((void**)&p216, g_p216);
    cudaGetSymbolAddress((void**)&a16,  g_a16);

    const int EB = (N_EDGES + 255) / 256;
    const int NB = (N_NODES + 255) / 256;   // 391
    const int GB = (N_NODES + 127) / 128;   // 782
    const int PB = N_NODES / 8;             // 12500

    const int SM_G2 = 53248 + 64 * 144;     // 62464
    const int SM_G3 = 53248 + 128 * 144;    // 71680
    cudaFuncSetAttribute(chain_k<256, 0, 64, true, true>,
                         cudaFuncAttributeMaxDynamicSharedMemorySize, SM_G2);
    cudaFuncSetAttribute(chain_k<256, 128, 128, false, true>,
                         cudaFuncAttributeMaxDynamicSharedMemorySize, SM_G3);

    // ---- graph preprocessing + BN stats ----
    detect_k<<<1, 256>>>((const int*)ei);
    zero_pre_k<<<NB, 256>>>();
    convert_k<<<EB, 256>>>(ei);
    dis_k<<<NB, 256>>>();
    blkred_k<<<NB, 256>>>();
    partscan_k<<<1, 512>>>(NB);
    blkscan_k<<<NB, 256>>>();
    csrfill_k<<<EB, 256>>>();
    bn_stats_k<<<512, 256>>>(x);
    bn_final_k<<<1, 128>>>(gamma, beta);

    // ---- layer 1: h = gelu(BN(x) @ W1 + b1), dual fp32+fp16 ----
    tgemm_k<128, 64, true, true, true><<<GB, 256>>>(
        x, x, x, x, 128, 0, 0, 0, W1, b1, bufh, h16);

    // ---- TAGConv1 props, then fused TAG1-GEMM + L2 ----
    prop_k<<<PB, 256>>>((const __half2*)h16,  (__half2*)p016);
    prop_k<<<PB, 256>>>((const __half2*)p016, (__half2*)p116);
    prop_k<<<PB, 256>>>((const __half2*)p116, (__half2*)p216);
    chain_k<256, 0, 64, true, true><<<GB, 256, SM_G2>>>(
        bufh, p016, p116, p216, 64, 64, 64, 0b1110,
        T1, t1b, nullptr, W2, b2, bufh, h16);

    // ---- TAGConv2 props, then fused TAG2-GEMM + L3 (a -> fp16) ----
    prop_k<<<PB, 256>>>((const __half2*)h16,  (__half2*)p016);
    prop_k<<<PB, 256>>>((const __half2*)p016, (__half2*)p116);
    prop_k<<<PB, 256>>>((const __half2*)p116, (__half2*)p216);
    chain_k<256, 128, 128, false, true><<<GB, 256, SM_G3>>>(
        bufh, p016, p116, p216, 64, 64, 64, 0b1110,
        T2, t2b, x, W3, b3, nullptr, a16);

    // ---- layer 4: out = a @ W4 + b4 (a is fp16) ----
    tgemm_k<128, 64, false, false, false><<<GB, 256>>>(
        a16, a16, a16, a16, 128, 0, 0, 1, W4, b4, out, nullptr);
}

// round 5
// speedup vs baseline: 1.9639x; 1.0692x over previous
#include <cuda_runtime.h>
#include <cuda_fp16.h>
#include <math.h>
#include <stdint.h>

#define N_NODES 100000
#define N_EDGES 1000000
#define AST 40   // As half stride
#define CST 72   // Cs half stride

// ---------------- device scratch ----------------
__device__ int   g_is64;
__device__ __align__(16) int   g_src[N_EDGES];
__device__ __align__(16) int   g_dst[N_EDGES];
__device__ __align__(16) int   g_degi[N_NODES];
__device__ __align__(16) float g_dis[N_NODES];
__device__ __align__(16) int   g_rowptr[N_NODES + 1];
__device__ __align__(16) int   g_fill[N_NODES];
__device__ __align__(16) int2  g_cw[N_EDGES];
__device__ __align__(16) int   g_part[512];
__device__ __align__(16) float g_bnsum[128];
__device__ __align__(16) float g_bnsq[128];
__device__ __align__(16) float g_bns[128];
__device__ __align__(16) float g_bnt[128];
__device__ __align__(16) __half g_x16 [N_NODES * 128];
__device__ __align__(16) __half g_a16 [N_NODES * 128];
__device__ __align__(16) __half g_h16 [N_NODES * 64];
__device__ __align__(16) __half g_p016[N_NODES * 64];
__device__ __align__(16) __half g_p116[N_NODES * 64];
__device__ __align__(16) __half g_p216[N_NODES * 64];

// ---------------- helpers ----------------
__device__ __forceinline__ float gelu_f(float v) {
    return 0.5f * v * (1.0f + erff(v * 0.70710678118654752440f));
}

__device__ __forceinline__ void mmaf16(float d[4], const uint32_t a[4],
                                       uint32_t b0, uint32_t b1) {
    asm volatile(
        "mma.sync.aligned.m16n8k16.row.col.f32.f16.f16.f32 "
        "{%0,%1,%2,%3}, {%4,%5,%6,%7}, {%8,%9}, {%0,%1,%2,%3};"
        : "+f"(d[0]), "+f"(d[1]), "+f"(d[2]), "+f"(d[3])
        : "r"(a[0]), "r"(a[1]), "r"(a[2]), "r"(a[3]), "r"(b0), "r"(b1));
}

// segmented A-tile fill (128 x 32) into half smem. Segments fp16 or fp32(+BN).
template <bool BNA>
__device__ __forceinline__ void fill_A_h(
    __half (*As)[AST], int m0, int k0,
    const void* p0_, const void* p1_, const void* p2_, const void* p3_,
    int w0, int w1, int w2, int KD, int fp16mask, int tid) {
    const void* Ap = p0_; int Aw = w0, cum = 0, seg = 0;
    if (k0 >= w0)           { Ap = p1_; Aw = w1; cum = w0; seg = 1; }
    if (k0 >= w0 + w1)      { Ap = p2_; Aw = w2; cum = w0 + w1; seg = 2; }
    if (k0 >= w0 + w1 + w2) { Ap = p3_; Aw = KD - w0 - w1 - w2; cum = w0 + w1 + w2; seg = 3; }
    int kloc = k0 - cum;
    bool is16 = (fp16mask >> seg) & 1;
#pragma unroll
    for (int pass = 0; pass < 4; pass++) {
        int r  = pass * 32 + (tid >> 3);
        int c4 = (tid & 7) * 4;
        int gr = m0 + r;
        uint2 u = make_uint2(0u, 0u);
        if (gr < N_NODES) {
            if (is16) {
                u = *(const uint2*)((const __half*)Ap + (size_t)gr * Aw + kloc + c4);
            } else {
                float4 v = *(const float4*)((const float*)Ap + (size_t)gr * Aw + kloc + c4);
                if (BNA) {
                    int kc = k0 + c4;
                    v.x = v.x * g_bns[kc]     + g_bnt[kc];
                    v.y = v.y * g_bns[kc + 1] + g_bnt[kc + 1];
                    v.z = v.z * g_bns[kc + 2] + g_bnt[kc + 2];
                    v.w = v.w * g_bns[kc + 3] + g_bnt[kc + 3];
                }
                __half2 h01 = __floats2half2_rn(v.x, v.y);
                __half2 h23 = __floats2half2_rn(v.z, v.w);
                u.x = *(uint32_t*)&h01;
                u.y = *(uint32_t*)&h23;
            }
        }
        *(uint2*)&As[r][c4] = u;
    }
}

// W tile fill: 32 x NOUT fp32 -> transposed fp16 hi/lo
__device__ __forceinline__ void fill_W_h(
    __half (*Wh)[AST], __half (*Wl)[AST],
    const float* __restrict__ W, int k0, int NOUT, int tid) {
    for (int idx = tid; idx < 32 * NOUT / 4; idx += 256) {
        int kr = idx / (NOUT / 4);
        int c4 = (idx % (NOUT / 4)) * 4;
        float4 wv = *(const float4*)(W + (size_t)(k0 + kr) * NOUT + c4);
        float wf[4] = {wv.x, wv.y, wv.z, wv.w};
#pragma unroll
        for (int q = 0; q < 4; q++) {
            __half h = __float2half_rn(wf[q]);
            Wh[c4 + q][kr] = h;
            Wl[c4 + q][kr] = __float2half_rn(wf[q] - __half2float(h));
        }
    }
}

// one 32-K step: fp16 A (exact), W hi/lo split -> 2 mmas per k16
template <int NT>
__device__ __forceinline__ void mma_tile_h(
    float d[2][NT][4], const __half* Ab, int astr,
    const __half (*Wh)[AST], const __half (*Wl)[AST],
    int Rm, int Cn, int gid, int tg) {
#pragma unroll
    for (int ks = 0; ks < 2; ks++) {
        int kk = ks * 16;
        uint32_t a[2][4];
#pragma unroll
        for (int mt = 0; mt < 2; mt++) {
            const __half* ap = Ab + (size_t)(Rm + mt * 16 + gid) * astr + kk + 2 * tg;
            a[mt][0] = *(const uint32_t*)ap;
            a[mt][1] = *(const uint32_t*)(ap + 8 * astr);
            a[mt][2] = *(const uint32_t*)(ap + 8);
            a[mt][3] = *(const uint32_t*)(ap + 8 * astr + 8);
        }
#pragma unroll
        for (int nt = 0; nt < NT; nt++) {
            int col = Cn + nt * 8 + gid;
            uint32_t bh0 = *(const uint32_t*)&Wh[col][kk + 2 * tg];
            uint32_t bh1 = *(const uint32_t*)&Wh[col][kk + 8 + 2 * tg];
            uint32_t bl0 = *(const uint32_t*)&Wl[col][kk + 2 * tg];
            uint32_t bl1 = *(const uint32_t*)&Wl[col][kk + 8 + 2 * tg];
#pragma unroll
            for (int mt = 0; mt < 2; mt++) {
                mmaf16(d[mt][nt], a[mt], bh0, bh1);
                mmaf16(d[mt][nt], a[mt], bl0, bl1);
            }
        }
    }
}

// ---------------- preprocessing ----------------
__global__ void detect_k(const int* __restrict__ ei) {
    __shared__ int anynz;
    if (threadIdx.x == 0) anynz = 0;
    __syncthreads();
    if (ei[threadIdx.x * 2 + 1] != 0) anynz = 1;
    __syncthreads();
    if (threadIdx.x == 0) g_is64 = (anynz == 0) ? 1 : 0;
}

__global__ void zero_deg_k() {
    int i = blockIdx.x * blockDim.x + threadIdx.x;
    if (i < N_NODES) g_degi[i] = 0;
}

__global__ void zero_bn_k() {
    g_bnsum[threadIdx.x] = 0.f;
    g_bnsq[threadIdx.x]  = 0.f;
}

__global__ void convert_k(const void* __restrict__ ei) {
    int e = blockIdx.x * blockDim.x + threadIdx.x;
    if (e >= N_EDGES) return;
    int s, d;
    if (g_is64) {
        const long long* p = (const long long*)ei;
        s = (int)p[e];
        d = (int)p[N_EDGES + e];
    } else {
        const int* p = (const int*)ei;
        s = p[e];
        d = p[N_EDGES + e];
    }
    g_src[e] = s;
    g_dst[e] = d;
    atomicAdd(&g_degi[d], 1);
}

__global__ void dis_k() {
    int i = blockIdx.x * blockDim.x + threadIdx.x;
    if (i >= N_NODES) return;
    int d = g_degi[i];
    g_dis[i] = (d > 0) ? rsqrtf((float)d) : 0.f;
}

__global__ void blkred_k() {
    __shared__ int ws[8];
    int i = blockIdx.x * 256 + threadIdx.x;
    int v = (i < N_NODES) ? g_degi[i] : 0;
#pragma unroll
    for (int o = 16; o; o >>= 1) v += __shfl_down_sync(0xffffffffu, v, o);
    if ((threadIdx.x & 31) == 0) ws[threadIdx.x >> 5] = v;
    __syncthreads();
    if (threadIdx.x < 8) {
        int t = ws[threadIdx.x];
#pragma unroll
        for (int o = 4; o; o >>= 1) t += __shfl_down_sync(0xffu, t, o);
        if (threadIdx.x == 0) g_part[blockIdx.x] = t;
    }
}

__global__ void partscan_k(int nb) {
    __shared__ int ws[16];
    int t = threadIdx.x, lane = t & 31, w = t >> 5;
    int v = (t < nb) ? g_part[t] : 0;
    int x = v;
#pragma unroll
    for (int o = 1; o < 32; o <<= 1) {
        int y = __shfl_up_sync(0xffffffffu, x, o);
        if (lane >= o) x += y;
    }
    if (lane == 31) ws[w] = x;
    __syncthreads();
    if (w == 0 && lane < 16) {
        int s = ws[lane];
#pragma unroll
        for (int o = 1; o < 16; o <<= 1) {
            int y = __shfl_up_sync(0x0000ffffu, s, o);
            if (lane >= o) s += y;
        }
        ws[lane] = s;
    }
    __syncthreads();
    int pre = (w ? ws[w - 1] : 0) + x - v;
    if (t < nb) g_part[t] = pre;
    if (t == nb - 1) g_rowptr[N_NODES] = pre + v;
}

__global__ void blkscan_k() {
    __shared__ int ws[8];
    int t = threadIdx.x, lane = t & 31, w = t >> 5;
    int i = blockIdx.x * 256 + t;
    int v = (i < N_NODES) ? g_degi[i] : 0;
    int x = v;
#pragma unroll
    for (int o = 1; o < 32; o <<= 1) {
        int y = __shfl_up_sync(0xffffffffu, x, o);
        if (lane >= o) x += y;
    }
    if (lane == 31) ws[w] = x;
    __syncthreads();
    if (w == 0 && lane < 8) {
        int s = ws[lane];
#pragma unroll
        for (int o = 1; o < 8; o <<= 1) {
            int y = __shfl_up_sync(0x000000ffu, s, o);
            if (lane >= o) s += y;
        }
        ws[lane] = s;
    }
    __syncthreads();
    int ex = g_part[blockIdx.x] + (w ? ws[w - 1] : 0) + x - v;
    if (i < N_NODES) { g_rowptr[i] = ex; g_fill[i] = ex; }
}

__global__ void csrfill_k() {
    int e = blockIdx.x * blockDim.x + threadIdx.x;
    if (e >= N_EDGES) return;
    int s = g_src[e], d = g_dst[e];
    int pos = atomicAdd(&g_fill[d], 1);
    g_cw[pos] = make_int2(s, __float_as_int(g_dis[s] * g_dis[d]));
}

// BN stats + emit fp16 copy of x (for L3 concat branch)
__global__ void bn_stats_k(const float* __restrict__ x) {
    int col = threadIdx.x & 127;
    int r = blockIdx.x * 2 + (threadIdx.x >> 7);
    float s = 0.f, q = 0.f;
    for (; r < N_NODES; r += gridDim.x * 2) {
        float v = x[(size_t)r * 128 + col];
        g_x16[(size_t)r * 128 + col] = __float2half_rn(v);
        s += v;
        q += v * v;
    }
    atomicAdd(&g_bnsum[col], s);
    atomicAdd(&g_bnsq[col], q);
}

__global__ void bn_final_k(const float* __restrict__ gamma, const float* __restrict__ beta) {
    int c = threadIdx.x;
    float mean = g_bnsum[c] * (1.0f / N_NODES);
    float var  = g_bnsq[c] * (1.0f / N_NODES) - mean * mean;
    float s = gamma[c] * rsqrtf(var + 1e-5f);
    g_bns[c] = s;
    g_bnt[c] = beta[c] - mean * s;
}

// CSR propagation, fp16 feats, packed (col,w), warp per node
__global__ void __launch_bounds__(256) prop_k(const __half2* __restrict__ in,
                                              __half2* __restrict__ out) {
    int node = (blockIdx.x << 3) + (threadIdx.x >> 5);
    int lane = threadIdx.x & 31;
    int beg = g_rowptr[node], end = g_rowptr[node + 1];
    float ax = 0.f, ay = 0.f;
    int e = beg;
    for (; e + 3 < end; e += 4) {
        int2 c0 = __ldg(g_cw + e),     c1 = __ldg(g_cw + e + 1);
        int2 c2 = __ldg(g_cw + e + 2), c3 = __ldg(g_cw + e + 3);
        float2 f0 = __half22float2(__ldg(in + (size_t)c0.x * 32 + lane));
        float2 f1 = __half22float2(__ldg(in + (size_t)c1.x * 32 + lane));
        float2 f2 = __half22float2(__ldg(in + (size_t)c2.x * 32 + lane));
        float2 f3 = __half22float2(__ldg(in + (size_t)c3.x * 32 + lane));
        float w0 = __int_as_float(c0.y), w1 = __int_as_float(c1.y);
        float w2 = __int_as_float(c2.y), w3 = __int_as_float(c3.y);
        ax = fmaf(w0, f0.x, fmaf(w1, f1.x, fmaf(w2, f2.x, fmaf(w3, f3.x, ax))));
        ay = fmaf(w0, f0.y, fmaf(w1, f1.y, fmaf(w2, f2.y, fmaf(w3, f3.y, ay))));
    }
    for (; e < end; e++) {
        int2 c0 = __ldg(g_cw + e);
        float2 f0 = __half22float2(__ldg(in + (size_t)c0.x * 32 + lane));
        float w0 = __int_as_float(c0.y);
        ax = fmaf(w0, f0.x, ax);
        ay = fmaf(w0, f0.y, ay);
    }
    out[(size_t)node * 32 + lane] = __float22half2_rn(make_float2(ax, ay));
}

// ---------------- standalone GEMM (L1, L4), NOUT=64 ----------------
template <int KD, bool ACT, bool BNA, bool OUT16>
__global__ void __launch_bounds__(256) tgemm_k(
    const void* __restrict__ p0_, const void* __restrict__ p1_,
    const void* __restrict__ p2_, const void* __restrict__ p3_,
    int w0, int w1, int w2, int fp16mask,
    const float* __restrict__ W, const float* __restrict__ bias,
    float* __restrict__ C, __half* __restrict__ C16) {
    __shared__ __half As[128][AST];
    __shared__ __half Wh[64][AST];
    __shared__ __half Wl[64][AST];

    int tid = threadIdx.x;
    int lane = tid & 31, wid = tid >> 5;
    int gid = lane >> 2, tg = lane & 3;
    int warp_m = wid & 3, warp_n = wid >> 2;
    int Rm = warp_m * 32;
    int Cn = warp_n * 32;
    int m0 = blockIdx.x * 128;

    float d[2][4][4];
#pragma unroll
    for (int mt = 0; mt < 2; mt++)
#pragma unroll
        for (int nt = 0; nt < 4; nt++)
#pragma unroll
            for (int q = 0; q < 4; q++) d[mt][nt][q] = 0.f;

    for (int k0 = 0; k0 < KD; k0 += 32) {
        fill_A_h<BNA>(As, m0, k0, p0_, p1_, p2_, p3_, w0, w1, w2, KD, fp16mask, tid);
        fill_W_h(Wh, Wl, W, k0, 64, tid);
        __syncthreads();
        mma_tile_h<4>(d, &As[0][0], AST, Wh, Wl, Rm, Cn, gid, tg);
        __syncthreads();
    }

#pragma unroll
    for (int mt = 0; mt < 2; mt++) {
#pragma unroll
        for (int nt = 0; nt < 4; nt++) {
            int col = Cn + nt * 8 + tg * 2;
            float bx = bias[col], by = bias[col + 1];
            int r0 = m0 + Rm + mt * 16 + gid;
            int r1 = r0 + 8;
            float v0 = d[mt][nt][0] + bx, v1 = d[mt][nt][1] + by;
            float v2 = d[mt][nt][2] + bx, v3 = d[mt][nt][3] + by;
            if (ACT) { v0 = gelu_f(v0); v1 = gelu_f(v1); v2 = gelu_f(v2); v3 = gelu_f(v3); }
            if (r0 < N_NODES) {
                if (OUT16) *(__half2*)(C16 + (size_t)r0 * 64 + col) =
                    __floats2half2_rn(v0, v1);
                else *(float2*)(C + (size_t)r0 * 64 + col) = make_float2(v0, v1);
            }
            if (r1 < N_NODES) {
                if (OUT16) *(__half2*)(C16 + (size_t)r1 * 64 + col) =
                    __floats2half2_rn(v2, v3);
                else *(float2*)(C + (size_t)r1 * 64 + col) = make_float2(v2, v3);
            }
        }
    }
}

// ---------------- fused 2-stage chain GEMM ----------------
// stage1: Cs(smem,fp16) = gelu(segs[K1=256] @ Wa + ba), N1=64
// stage2: out = gelu(concat(x16[XW], Cs) @ Wb + bb), N2 -> fp16 global
template <int XW, int N2>
__global__ void __launch_bounds__(256) chain_k(
    const void* __restrict__ p0_, const void* __restrict__ p1_,
    const void* __restrict__ p2_, const void* __restrict__ p3_,
    const float* __restrict__ Wa, const float* __restrict__ ba,
    const __half* __restrict__ xg,
    const float* __restrict__ Wb, const float* __restrict__ bb,
    __half* __restrict__ C16) {
    constexpr int NW = (N2 > 64) ? N2 : 64;
    extern __shared__ char sm[];
    __half (*As)[AST] = (__half(*)[AST])(sm);                       // 10240 B
    __half (*Cs)[CST] = (__half(*)[CST])(sm + 10240);               // 18432 B
    __half (*Wh)[AST] = (__half(*)[AST])(sm + 28672);
    __half (*Wl)[AST] = (__half(*)[AST])(sm + 28672 + NW * AST * 2);

    int tid = threadIdx.x;
    int lane = tid & 31, wid = tid >> 5;
    int gid = lane >> 2, tg = lane & 3;
    int warp_m = wid & 3, warp_n = wid >> 2;
    int Rm = warp_m * 32;
    int m0 = blockIdx.x * 128;

    // -------- stage 1: K=256, N=64 --------
    {
        int Cn = warp_n * 32;
        float d[2][4][4];
#pragma unroll
        for (int mt = 0; mt < 2; mt++)
#pragma unroll
            for (int nt = 0; nt < 4; nt++)
#pragma unroll
                for (int q = 0; q < 4; q++) d[mt][nt][q] = 0.f;

        for (int k0 = 0; k0 < 256; k0 += 32) {
            fill_A_h<false>(As, m0, k0, p0_, p1_, p2_, p3_, 64, 64, 64, 256, 0b1111, tid);
            fill_W_h(Wh, Wl, Wa, k0, 64, tid);
            __syncthreads();
            mma_tile_h<4>(d, &As[0][0], AST, Wh, Wl, Rm, Cn, gid, tg);
            __syncthreads();
        }
#pragma unroll
        for (int mt = 0; mt < 2; mt++) {
#pragma unroll
            for (int nt = 0; nt < 4; nt++) {
                int col = Cn + nt * 8 + tg * 2;
                float bx = ba[col], by = ba[col + 1];
                int r0 = Rm + mt * 16 + gid;
                *(__half2*)&Cs[r0][col] =
                    __floats2half2_rn(gelu_f(d[mt][nt][0] + bx), gelu_f(d[mt][nt][1] + by));
                *(__half2*)&Cs[r0 + 8][col] =
                    __floats2half2_rn(gelu_f(d[mt][nt][2] + bx), gelu_f(d[mt][nt][3] + by));
            }
        }
    }
    __syncthreads();

    // -------- stage 2: K = XW + 64, N = N2 --------
    {
        constexpr int NT = N2 / 16;
        int Cn = warp_n * (N2 / 2);
        float d[2][NT][4];
#pragma unroll
        for (int mt = 0; mt < 2; mt++)
#pragma unroll
            for (int nt = 0; nt < NT; nt++)
#pragma unroll
                for (int q = 0; q < 4; q++) d[mt][nt][q] = 0.f;

        for (int k0 = 0; k0 < XW + 64; k0 += 32) {
            bool from_x = (XW > 0) && (k0 < XW);
            if (from_x)
                fill_A_h<false>(As, m0, k0, xg, xg, xg, xg, XW, 0, 0, XW, 1, tid);
            fill_W_h(Wh, Wl, Wb, k0, N2, tid);
            __syncthreads();
            const __half* Ab = from_x ? &As[0][0] : &Cs[0][k0 - XW];
            int astr = from_x ? AST : CST;
            mma_tile_h<NT>(d, Ab, astr, Wh, Wl, Rm, Cn, gid, tg);
            __syncthreads();
        }

#pragma unroll
        for (int mt = 0; mt < 2; mt++) {
#pragma unroll
            for (int nt = 0; nt < NT; nt++) {
                int col = Cn + nt * 8 + tg * 2;
                float bx = bb[col], by = bb[col + 1];
                int r0 = m0 + Rm + mt * 16 + gid;
                int r1 = r0 + 8;
                float v0 = gelu_f(d[mt][nt][0] + bx), v1 = gelu_f(d[mt][nt][1] + by);
                float v2 = gelu_f(d[mt][nt][2] + bx), v3 = gelu_f(d[mt][nt][3] + by);
                if (r0 < N_NODES)
                    *(__half2*)(C16 + (size_t)r0 * N2 + col) = __floats2half2_rn(v0, v1);
                if (r1 < N_NODES)
                    *(__half2*)(C16 + (size_t)r1 * N2 + col) = __floats2half2_rn(v2, v3);
            }
        }
    }
}

// ---------------- host launcher ----------------
extern "C" void kernel_launch(void* const* d_in, const int* in_sizes, int n_in,
                              void* d_out, int out_size) {
    const float* x     = (const float*)d_in[0];
    const void*  ei    = d_in[1];
    const float* gamma = (const float*)d_in[2];
    const float* beta  = (const float*)d_in[3];
    const float* W1 = (const float*)d_in[4];  const float* b1  = (const float*)d_in[5];
    const float* T1 = (const float*)d_in[6];  const float* t1b = (const float*)d_in[7];
    const float* W2 = (const float*)d_in[8];  const float* b2  = (const float*)d_in[9];
    const float* T2 = (const float*)d_in[10]; const float* t2b = (const float*)d_in[11];
    const float* W3 = (const float*)d_in[12]; const float* b3  = (const float*)d_in[13];
    const float* W4 = (const float*)d_in[14]; const float* b4  = (const float*)d_in[15];
    float* out = (float*)d_out;

    __half *x16, *h16, *p016, *p116, *p216, *a16;
    cudaGetSymbolAddress((void**)&x16,  g_x16);
    cudaGetSymbolAddress((void**)&h16,  g_h16);
    cudaGetSymbolAddress((void**)&p016, g_p016);
    cudaGetSymbolAddress((void**)&p116, g_p116);
    cudaGetSymbolAddress((void**)&p216, g_p216);
    cudaGetSymbolAddress((void**)&a16,  g_a16);

    const int EB = (N_EDGES + 255) / 256;
    const int NB = (N_NODES + 255) / 256;   // 391
    const int GB = (N_NODES + 127) / 128;   // 782
    const int PB = N_NODES / 8;             // 12500

    const int SM_C1 = 28672 + 64  * AST * 4;  // 38912
    const int SM_C2 = 28672 + 128 * AST * 4;  // 49152
    cudaFuncSetAttribute(chain_k<0, 64>,
                         cudaFuncAttributeMaxDynamicSharedMemorySize, SM_C1);
    cudaFuncSetAttribute(chain_k<128, 128>,
                         cudaFuncAttributeMaxDynamicSharedMemorySize, SM_C2);

    // fork a side stream inside capture: BN + L1 overlap graph preprocessing
    cudaStream_t s1;
    cudaStreamCreateWithFlags(&s1, cudaStreamNonBlocking);
    cudaEvent_t e0, e1;
    cudaEventCreateWithFlags(&e0, cudaEventDisableTiming);
    cudaEventCreateWithFlags(&e1, cudaEventDisableTiming);
    cudaEventRecord(e0, 0);
    cudaStreamWaitEvent(s1, e0, 0);

    // ---- stream s1: BN stats (+x16 emit) -> BN final -> L1 GEMM ----
    zero_bn_k<<<1, 128, 0, s1>>>();
    bn_stats_k<<<512, 256, 0, s1>>>(x);
    bn_final_k<<<1, 128, 0, s1>>>(gamma, beta);
    tgemm_k<128, true, true, true><<<GB, 256, 0, s1>>>(
        x, x, x, x, 128, 0, 0, 0, W1, b1, nullptr, h16);
    cudaEventRecord(e1, s1);

    // ---- stream 0: graph preprocessing ----
    detect_k<<<1, 256>>>((const int*)ei);
    zero_deg_k<<<NB, 256>>>();
    convert_k<<<EB, 256>>>(ei);
    dis_k<<<NB, 256>>>();
    blkred_k<<<NB, 256>>>();
    partscan_k<<<1, 512>>>(NB);
    blkscan_k<<<NB, 256>>>();
    csrfill_k<<<EB, 256>>>();

    cudaStreamWaitEvent(0, e1, 0);   // join: props need CSR + h16

    // ---- TAGConv1 props + fused TAG1-GEMM + L2 -> h16 ----
    prop_k<<<PB, 256>>>((const __half2*)h16,  (__half2*)p016);
    prop_k<<<PB, 256>>>((const __half2*)p016, (__half2*)p116);
    prop_k<<<PB, 256>>>((const __half2*)p116, (__half2*)p216);
    chain_k<0, 64><<<GB, 256, SM_C1>>>(
        h16, p016, p116, p216, T1, t1b, nullptr, W2, b2, h16);

    // ---- TAGConv2 props + fused TAG2-GEMM + L3 -> a16 ----
    prop_k<<<PB, 256>>>((const __half2*)h16,  (__half2*)p016);
    prop_k<<<PB, 256>>>((const __half2*)p016, (__half2*)p116);
    prop_k<<<PB, 256>>>((const __half2*)p116, (__half2*)p216);
    chain_k<128, 128><<<GB, 256, SM_C2>>>(
        h16, p016, p116, p216, T2, t2b, x16, W3, b3, a16);

    // ---- layer 4: out = a @ W4 + b4 (fp32 out) ----
    tgemm_k<128, false, false, false><<<GB, 256>>>(
        a16, a16, a16, a16, 128, 0, 0, 1, W4, b4, out, nullptr);
}

// round 6
// speedup vs baseline: 2.5255x; 1.2859x over previous
#include <cuda_runtime.h>
#include <cuda_fp16.h>
#include <math.h>
#include <stdint.h>

#define N_NODES 100000
#define N_EDGES 1000000
#define AST 40   // As / W-tile half stride (conflict-free for ldmatrix)
#define CST 72   // Cs half stride

// ---------------- device scratch ----------------
__device__ int   g_is64;
__device__ __align__(16) int   g_src[N_EDGES];
__device__ __align__(16) int   g_dst[N_EDGES];
__device__ __align__(16) int   g_degi[N_NODES];
__device__ __align__(16) float g_dis[N_NODES];
__device__ __align__(16) int   g_rowptr[N_NODES + 1];
__device__ __align__(16) int   g_fill[N_NODES];
__device__ __align__(16) int2  g_cw[N_EDGES];
__device__ __align__(16) int   g_part[512];
__device__ __align__(16) float g_bnsum[128];
__device__ __align__(16) float g_bnsq[128];
__device__ __align__(16) float g_bns[128];
__device__ __align__(16) float g_bnt[128];
__device__ __align__(16) __half g_x16 [N_NODES * 128];
__device__ __align__(16) __half g_a16 [N_NODES * 128];
__device__ __align__(16) __half g_h16 [N_NODES * 64];
__device__ __align__(16) __half g_p016[N_NODES * 64];
__device__ __align__(16) __half g_p116[N_NODES * 64];
__device__ __align__(16) __half g_p216[N_NODES * 64];
// pre-split transposed weights: hi/lo fp16, [N][K] k-major
// offsets: W1=0(8192) T1=8192(16384) W2=24576(4096) T2=28672(16384)
//          W3=45056(24576) W4=69632(8192)  total 77824
__device__ __align__(16) __half g_wthi[77824];
__device__ __align__(16) __half g_wtlo[77824];

// ---------------- helpers ----------------
__device__ __forceinline__ float gelu_f(float v) {
    return 0.5f * v * (1.0f + erff(v * 0.70710678118654752440f));
}

__device__ __forceinline__ void mmaf16(float d[4], const uint32_t a[4],
                                       uint32_t b0, uint32_t b1) {
    asm volatile(
        "mma.sync.aligned.m16n8k16.row.col.f32.f16.f16.f32 "
        "{%0,%1,%2,%3}, {%4,%5,%6,%7}, {%8,%9}, {%0,%1,%2,%3};"
        : "+f"(d[0]), "+f"(d[1]), "+f"(d[2]), "+f"(d[3])
        : "r"(a[0]), "r"(a[1]), "r"(a[2]), "r"(a[3]), "r"(b0), "r"(b1));
}

__device__ __forceinline__ void ldsm_x4(uint32_t r[4], uint32_t a) {
    asm volatile("ldmatrix.sync.aligned.m8n8.x4.shared.b16 {%0,%1,%2,%3}, [%4];"
        : "=r"(r[0]), "=r"(r[1]), "=r"(r[2]), "=r"(r[3]) : "r"(a));
}

__device__ __forceinline__ uint32_t smaddr(const void* p) {
    return (uint32_t)__cvta_generic_to_shared(p);
}

// segmented A-tile fill (128 x 32) into half smem. Segments fp16 or fp32(+BN).
template <bool BNA>
__device__ __forceinline__ void fill_A_h(
    __half (*As)[AST], int m0, int k0,
    const void* p0_, const void* p1_, const void* p2_, const void* p3_,
    int w0, int w1, int w2, int KD, int fp16mask, int tid) {
    const void* Ap = p0_; int Aw = w0, cum = 0, seg = 0;
    if (k0 >= w0)           { Ap = p1_; Aw = w1; cum = w0; seg = 1; }
    if (k0 >= w0 + w1)      { Ap = p2_; Aw = w2; cum = w0 + w1; seg = 2; }
    if (k0 >= w0 + w1 + w2) { Ap = p3_; Aw = KD - w0 - w1 - w2; cum = w0 + w1 + w2; seg = 3; }
    int kloc = k0 - cum;
    bool is16 = (fp16mask >> seg) & 1;
#pragma unroll
    for (int pass = 0; pass < 4; pass++) {
        int r  = pass * 32 + (tid >> 3);
        int c4 = (tid & 7) * 4;
        int gr = m0 + r;
        uint2 u = make_uint2(0u, 0u);
        if (gr < N_NODES) {
            if (is16) {
                u = *(const uint2*)((const __half*)Ap + (size_t)gr * Aw + kloc + c4);
            } else {
                float4 v = *(const float4*)((const float*)Ap + (size_t)gr * Aw + kloc + c4);
                if (BNA) {
                    int kc = k0 + c4;
                    v.x = v.x * g_bns[kc]     + g_bnt[kc];
                    v.y = v.y * g_bns[kc + 1] + g_bnt[kc + 1];
                    v.z = v.z * g_bns[kc + 2] + g_bnt[kc + 2];
                    v.w = v.w * g_bns[kc + 3] + g_bnt[kc + 3];
                }
                __half2 h01 = __floats2half2_rn(v.x, v.y);
                __half2 h23 = __floats2half2_rn(v.z, v.w);
                u.x = *(uint32_t*)&h01;
                u.y = *(uint32_t*)&h23;
            }
        }
        *(uint2*)&As[r][c4] = u;
    }
}

// W-tile fill: pure uint4 copies from pre-split transposed weights [NOUT][Kfull]
template <int NOUT>
__device__ __forceinline__ void fill_W_cp(
    __half (*Wh)[AST], __half (*Wl)[AST],
    const __half* __restrict__ Whg, const __half* __restrict__ Wlg,
    int Kfull, int k0, int tid) {
#pragma unroll
    for (int i = 0; i < NOUT / 64; i++) {
        int idx = i * 256 + tid;
        int row = idx >> 2;
        int c8  = (idx & 3) * 8;
        *(uint4*)&Wh[row][c8] = *(const uint4*)(Whg + (size_t)row * Kfull + k0 + c8);
        *(uint4*)&Wl[row][c8] = *(const uint4*)(Wlg + (size_t)row * Kfull + k0 + c8);
    }
}

// one 32-K step of mma with ldmatrix fragments.
// Ab_addr: smem addr of A tile element [0][k_tile_start], stride astr (halfs)
template <int NT>
__device__ __forceinline__ void mma_tile_l(
    float d[2][NT][4], uint32_t Ab_addr, int astr,
    uint32_t Wh_addr, uint32_t Wl_addr,
    int Rm, int Cn, int lane) {
#pragma unroll
    for (int ks = 0; ks < 2; ks++) {
        int kk = ks * 16;
        uint32_t a[2][4];
#pragma unroll
        for (int mt = 0; mt < 2; mt++) {
            int row = Rm + 16 * mt + (lane & 15);
            int kof = kk + 8 * (lane >> 4);
            ldsm_x4(a[mt], Ab_addr + ((row * astr + kof) << 1));
        }
        uint32_t bh[NT / 2][4], bl[NT / 2][4];
#pragma unroll
        for (int q = 0; q < NT / 2; q++) {
            int row = Cn + q * 16 + (lane & 7) + ((lane >> 4) << 3);
            int kof = kk + 8 * ((lane >> 3) & 1);
            uint32_t off = (uint32_t)((row * AST + kof) << 1);
            ldsm_x4(bh[q], Wh_addr + off);
            ldsm_x4(bl[q], Wl_addr + off);
        }
#pragma unroll
        for (int q = 0; q < NT / 2; q++) {
#pragma unroll
            for (int h = 0; h < 2; h++) {
                int nt = q * 2 + h;
#pragma unroll
                for (int mt = 0; mt < 2; mt++) {
                    mmaf16(d[mt][nt], a[mt], bh[q][2 * h], bh[q][2 * h + 1]);
                    mmaf16(d[mt][nt], a[mt], bl[q][2 * h], bl[q][2 * h + 1]);
                }
            }
        }
    }
}

// ---------------- preprocessing ----------------
__global__ void detect_k(const int* __restrict__ ei) {
    __shared__ int anynz;
    if (threadIdx.x == 0) anynz = 0;
    __syncthreads();
    if (ei[threadIdx.x * 2 + 1] != 0) anynz = 1;
    __syncthreads();
    if (threadIdx.x == 0) g_is64 = (anynz == 0) ? 1 : 0;
}

__global__ void zero_deg_k() {
    int i = blockIdx.x * blockDim.x + threadIdx.x;
    if (i < N_NODES) g_degi[i] = 0;
}

__global__ void zero_bn_k() {
    g_bnsum[threadIdx.x] = 0.f;
    g_bnsq[threadIdx.x]  = 0.f;
}

// pre-split one weight matrix: src fp32 [K][N] -> dst hi/lo fp16 [N][K]
__global__ void prepw_k(const float* __restrict__ src,
                        __half* __restrict__ dhi, __half* __restrict__ dlo,
                        int K, int N) {
    int idx = blockIdx.x * 256 + threadIdx.x;
    if (idx >= K * N) return;
    int k = idx / N, n = idx - k * N;
    float w = src[idx];
    __half h = __float2half_rn(w);
    dhi[(size_t)n * K + k] = h;
    dlo[(size_t)n * K + k] = __float2half_rn(w - __half2float(h));
}

__global__ void convert_k(const void* __restrict__ ei) {
    int e = blockIdx.x * blockDim.x + threadIdx.x;
    if (e >= N_EDGES) return;
    int s, d;
    if (g_is64) {
        const long long* p = (const long long*)ei;
        s = (int)p[e];
        d = (int)p[N_EDGES + e];
    } else {
        const int* p = (const int*)ei;
        s = p[e];
        d = p[N_EDGES + e];
    }
    g_src[e] = s;
    g_dst[e] = d;
    atomicAdd(&g_degi[d], 1);
}

__global__ void dis_k() {
    int i = blockIdx.x * blockDim.x + threadIdx.x;
    if (i >= N_NODES) return;
    int d = g_degi[i];
    g_dis[i] = (d > 0) ? rsqrtf((float)d) : 0.f;
}

__global__ void blkred_k() {
    __shared__ int ws[8];
    int i = blockIdx.x * 256 + threadIdx.x;
    int v = (i < N_NODES) ? g_degi[i] : 0;
#pragma unroll
    for (int o = 16; o; o >>= 1) v += __shfl_down_sync(0xffffffffu, v, o);
    if ((threadIdx.x & 31) == 0) ws[threadIdx.x >> 5] = v;
    __syncthreads();
    if (threadIdx.x < 8) {
        int t = ws[threadIdx.x];
#pragma unroll
        for (int o = 4; o; o >>= 1) t += __shfl_down_sync(0xffu, t, o);
        if (threadIdx.x == 0) g_part[blockIdx.x] = t;
    }
}

__global__ void partscan_k(int nb) {
    __shared__ int ws[16];
    int t = threadIdx.x, lane = t & 31, w = t >> 5;
    int v = (t < nb) ? g_part[t] : 0;
    int x = v;
#pragma unroll
    for (int o = 1; o < 32; o <<= 1) {
        int y = __shfl_up_sync(0xffffffffu, x, o);
        if (lane >= o) x += y;
    }
    if (lane == 31) ws[w] = x;
    __syncthreads();
    if (w == 0 && lane < 16) {
        int s = ws[lane];
#pragma unroll
        for (int o = 1; o < 16; o <<= 1) {
            int y = __shfl_up_sync(0x0000ffffu, s, o);
            if (lane >= o) s += y;
        }
        ws[lane] = s;
    }
    __syncthreads();
    int pre = (w ? ws[w - 1] : 0) + x - v;
    if (t < nb) g_part[t] = pre;
    if (t == nb - 1) g_rowptr[N_NODES] = pre + v;
}

__global__ void blkscan_k() {
    __shared__ int ws[8];
    int t = threadIdx.x, lane = t & 31, w = t >> 5;
    int i = blockIdx.x * 256 + t;
    int v = (i < N_NODES) ? g_degi[i] : 0;
    int x = v;
#pragma unroll
    for (int o = 1; o < 32; o <<= 1) {
        int y = __shfl_up_sync(0xffffffffu, x, o);
        if (lane >= o) x += y;
    }
    if (lane == 31) ws[w] = x;
    __syncthreads();
    if (w == 0 && lane < 8) {
        int s = ws[lane];
#pragma unroll
        for (int o = 1; o < 8; o <<= 1) {
            int y = __shfl_up_sync(0x000000ffu, s, o);
            if (lane >= o) s += y;
        }
        ws[lane] = s;
    }
    __syncthreads();
    int ex = g_part[blockIdx.x] + (w ? ws[w - 1] : 0) + x - v;
    if (i < N_NODES) { g_rowptr[i] = ex; g_fill[i] = ex; }
}

__global__ void csrfill_k() {
    int e = blockIdx.x * blockDim.x + threadIdx.x;
    if (e >= N_EDGES) return;
    int s = g_src[e], d = g_dst[e];
    int pos = atomicAdd(&g_fill[d], 1);
    g_cw[pos] = make_int2(s, __float_as_int(g_dis[s] * g_dis[d]));
}

// BN stats + emit fp16 copy of x
__global__ void bn_stats_k(const float* __restrict__ x) {
    int col = threadIdx.x & 127;
    int r = blockIdx.x * 2 + (threadIdx.x >> 7);
    float s = 0.f, q = 0.f;
    for (; r < N_NODES; r += gridDim.x * 2) {
        float v = x[(size_t)r * 128 + col];
        g_x16[(size_t)r * 128 + col] = __float2half_rn(v);
        s += v;
        q += v * v;
    }
    atomicAdd(&g_bnsum[col], s);
    atomicAdd(&g_bnsq[col], q);
}

__global__ void bn_final_k(const float* __restrict__ gamma, const float* __restrict__ beta) {
    int c = threadIdx.x;
    float mean = g_bnsum[c] * (1.0f / N_NODES);
    float var  = g_bnsq[c] * (1.0f / N_NODES) - mean * mean;
    float s = gamma[c] * rsqrtf(var + 1e-5f);
    g_bns[c] = s;
    g_bnt[c] = beta[c] - mean * s;
}

// CSR propagation, fp16 feats, packed (col,w), warp per node
__global__ void __launch_bounds__(256) prop_k(const __half2* __restrict__ in,
                                              __half2* __restrict__ out) {
    int node = (blockIdx.x << 3) + (threadIdx.x >> 5);
    int lane = threadIdx.x & 31;
    int beg = g_rowptr[node], end = g_rowptr[node + 1];
    float ax = 0.f, ay = 0.f;
    int e = beg;
    for (; e + 3 < end; e += 4) {
        int2 c0 = __ldg(g_cw + e),     c1 = __ldg(g_cw + e + 1);
        int2 c2 = __ldg(g_cw + e + 2), c3 = __ldg(g_cw + e + 3);
        float2 f0 = __half22float2(__ldg(in + (size_t)c0.x * 32 + lane));
        float2 f1 = __half22float2(__ldg(in + (size_t)c1.x * 32 + lane));
        float2 f2 = __half22float2(__ldg(in + (size_t)c2.x * 32 + lane));
        float2 f3 = __half22float2(__ldg(in + (size_t)c3.x * 32 + lane));
        float w0 = __int_as_float(c0.y), w1 = __int_as_float(c1.y);
        float w2 = __int_as_float(c2.y), w3 = __int_as_float(c3.y);
        ax = fmaf(w0, f0.x, fmaf(w1, f1.x, fmaf(w2, f2.x, fmaf(w3, f3.x, ax))));
        ay = fmaf(w0, f0.y, fmaf(w1, f1.y, fmaf(w2, f2.y, fmaf(w3, f3.y, ay))));
    }
    for (; e < end; e++) {
        int2 c0 = __ldg(g_cw + e);
        float2 f0 = __half22float2(__ldg(in + (size_t)c0.x * 32 + lane));
        float w0 = __int_as_float(c0.y);
        ax = fmaf(w0, f0.x, ax);
        ay = fmaf(w0, f0.y, ay);
    }
    out[(size_t)node * 32 + lane] = __float22half2_rn(make_float2(ax, ay));
}

// ---------------- standalone GEMM (L1, L4), NOUT=64 ----------------
template <int KD, bool ACT, bool BNA, bool OUT16>
__global__ void __launch_bounds__(256) tgemm_k(
    const void* __restrict__ p0_, const void* __restrict__ p1_,
    const void* __restrict__ p2_, const void* __restrict__ p3_,
    int w0, int w1, int w2, int fp16mask,
    const __half* __restrict__ Whg, const __half* __restrict__ Wlg,
    const float* __restrict__ bias,
    float* __restrict__ C, __half* __restrict__ C16) {
    __shared__ __half As[128][AST];
    __shared__ __half Wh[64][AST];
    __shared__ __half Wl[64][AST];

    int tid = threadIdx.x;
    int lane = tid & 31, wid = tid >> 5;
    int gid = lane >> 2, tg = lane & 3;
    int warp_m = wid & 3, warp_n = wid >> 2;
    int Rm = warp_m * 32;
    int Cn = warp_n * 32;
    int m0 = blockIdx.x * 128;

    uint32_t as_a = smaddr(&As[0][0]);
    uint32_t wh_a = smaddr(&Wh[0][0]);
    uint32_t wl_a = smaddr(&Wl[0][0]);

    float d[2][4][4];
#pragma unroll
    for (int mt = 0; mt < 2; mt++)
#pragma unroll
        for (int nt = 0; nt < 4; nt++)
#pragma unroll
            for (int q = 0; q < 4; q++) d[mt][nt][q] = 0.f;

    for (int k0 = 0; k0 < KD; k0 += 32) {
        fill_A_h<BNA>(As, m0, k0, p0_, p1_, p2_, p3_, w0, w1, w2, KD, fp16mask, tid);
        fill_W_cp<64>(Wh, Wl, Whg, Wlg, KD, k0, tid);
        __syncthreads();
        mma_tile_l<4>(d, as_a, AST, wh_a, wl_a, Rm, Cn, lane);
        __syncthreads();
    }

#pragma unroll
    for (int mt = 0; mt < 2; mt++) {
#pragma unroll
        for (int nt = 0; nt < 4; nt++) {
            int col = Cn + nt * 8 + tg * 2;
            float bx = bias[col], by = bias[col + 1];
            int r0 = m0 + Rm + mt * 16 + gid;
            int r1 = r0 + 8;
            float v0 = d[mt][nt][0] + bx, v1 = d[mt][nt][1] + by;
            float v2 = d[mt][nt][2] + bx, v3 = d[mt][nt][3] + by;
            if (ACT) { v0 = gelu_f(v0); v1 = gelu_f(v1); v2 = gelu_f(v2); v3 = gelu_f(v3); }
            if (r0 < N_NODES) {
                if (OUT16) *(__half2*)(C16 + (size_t)r0 * 64 + col) =
                    __floats2half2_rn(v0, v1);
                else *(float2*)(C + (size_t)r0 * 64 + col) = make_float2(v0, v1);
            }
            if (r1 < N_NODES) {
                if (OUT16) *(__half2*)(C16 + (size_t)r1 * 64 + col) =
                    __floats2half2_rn(v2, v3);
                else *(float2*)(C + (size_t)r1 * 64 + col) = make_float2(v2, v3);
            }
        }
    }
}

// ---------------- fused 2-stage chain GEMM ----------------
template <int XW, int N2>
__global__ void __launch_bounds__(256) chain_k(
    const void* __restrict__ p0_, const void* __restrict__ p1_,
    const void* __restrict__ p2_, const void* __restrict__ p3_,
    const __half* __restrict__ Wahg, const __half* __restrict__ Walg,
    const float* __restrict__ ba,
    const __half* __restrict__ xg,
    const __half* __restrict__ Wbhg, const __half* __restrict__ Wblg,
    const float* __restrict__ bb,
    __half* __restrict__ C16) {
    constexpr int NW = (N2 > 64) ? N2 : 64;
    extern __shared__ char sm[];
    __half (*As)[AST] = (__half(*)[AST])(sm);                      // 10240 B
    __half (*Cs)[CST] = (__half(*)[CST])(sm + 10240);              // 18432 B
    __half (*Wh)[AST] = (__half(*)[AST])(sm + 28672);
    __half (*Wl)[AST] = (__half(*)[AST])(sm + 28672 + NW * AST * 2);

    int tid = threadIdx.x;
    int lane = tid & 31, wid = tid >> 5;
    int gid = lane >> 2, tg = lane & 3;
    int warp_m = wid & 3, warp_n = wid >> 2;
    int Rm = warp_m * 32;
    int m0 = blockIdx.x * 128;

    uint32_t as_a = smaddr(&As[0][0]);
    uint32_t cs_a = smaddr(&Cs[0][0]);
    uint32_t wh_a = smaddr(&Wh[0][0]);
    uint32_t wl_a = smaddr(&Wl[0][0]);

    // -------- stage 1: K=256, N=64 --------
    {
        int Cn = warp_n * 32;
        float d[2][4][4];
#pragma unroll
        for (int mt = 0; mt < 2; mt++)
#pragma unroll
            for (int nt = 0; nt < 4; nt++)
#pragma unroll
                for (int q = 0; q < 4; q++) d[mt][nt][q] = 0.f;

        for (int k0 = 0; k0 < 256; k0 += 32) {
            fill_A_h<false>(As, m0, k0, p0_, p1_, p2_, p3_, 64, 64, 64, 256, 0b1111, tid);
            fill_W_cp<64>(Wh, Wl, Wahg, Walg, 256, k0, tid);
            __syncthreads();
            mma_tile_l<4>(d, as_a, AST, wh_a, wl_a, Rm, Cn, lane);
            __syncthreads();
        }
#pragma unroll
        for (int mt = 0; mt < 2; mt++) {
#pragma unroll
            for (int nt = 0; nt < 4; nt++) {
                int col = Cn + nt * 8 + tg * 2;
                float bx = ba[col], by = ba[col + 1];
                int r0 = Rm + mt * 16 + gid;
                *(__half2*)&Cs[r0][col] =
                    __floats2half2_rn(gelu_f(d[mt][nt][0] + bx), gelu_f(d[mt][nt][1] + by));
                *(__half2*)&Cs[r0 + 8][col] =
                    __floats2half2_rn(gelu_f(d[mt][nt][2] + bx), gelu_f(d[mt][nt][3] + by));
            }
        }
    }
    __syncthreads();

    // -------- stage 2: K = XW + 64, N = N2 --------
    {
        constexpr int NT = N2 / 16;
        int Cn = warp_n * (N2 / 2);
        float d[2][NT][4];
#pragma unroll
        for (int mt = 0; mt < 2; mt++)
#pragma unroll
            for (int nt = 0; nt < NT; nt++)
#pragma unroll
                for (int q = 0; q < 4; q++) d[mt][nt][q] = 0.f;

        for (int k0 = 0; k0 < XW + 64; k0 += 32) {
            bool from_x = (XW > 0) && (k0 < XW);
            if (from_x)
                fill_A_h<false>(As, m0, k0, xg, xg, xg, xg, XW, 0, 0, XW, 1, tid);
            fill_W_cp<NW>(Wh, Wl, Wbhg, Wblg, XW + 64, k0, tid);
            __syncthreads();
            uint32_t Ab = from_x ? as_a : (cs_a + ((k0 - XW) << 1));
            int astr = from_x ? AST : CST;
            mma_tile_l<NT>(d, Ab, astr, wh_a, wl_a, Rm, Cn, lane);
            __syncthreads();
        }

#pragma unroll
        for (int mt = 0; mt < 2; mt++) {
#pragma unroll
            for (int nt = 0; nt < NT; nt++) {
                int col = Cn + nt * 8 + tg * 2;
                float bx = bb[col], by = bb[col + 1];
                int r0 = m0 + Rm + mt * 16 + gid;
                int r1 = r0 + 8;
                float v0 = gelu_f(d[mt][nt][0] + bx), v1 = gelu_f(d[mt][nt][1] + by);
                float v2 = gelu_f(d[mt][nt][2] + bx), v3 = gelu_f(d[mt][nt][3] + by);
                if (r0 < N_NODES)
                    *(__half2*)(C16 + (size_t)r0 * N2 + col) = __floats2half2_rn(v0, v1);
                if (r1 < N_NODES)
                    *(__half2*)(C16 + (size_t)r1 * N2 + col) = __floats2half2_rn(v2, v3);
            }
        }
    }
}

// ---------------- host launcher ----------------
extern "C" void kernel_launch(void* const* d_in, const int* in_sizes, int n_in,
                              void* d_out, int out_size) {
    const float* x     = (const float*)d_in[0];
    const void*  ei    = d_in[1];
    const float* gamma = (const float*)d_in[2];
    const float* beta  = (const float*)d_in[3];
    const float* W1 = (const float*)d_in[4];  const float* b1  = (const float*)d_in[5];
    const float* T1 = (const float*)d_in[6];  const float* t1b = (const float*)d_in[7];
    const float* W2 = (const float*)d_in[8];  const float* b2  = (const float*)d_in[9];
    const float* T2 = (const float*)d_in[10]; const float* t2b = (const float*)d_in[11];
    const float* W3 = (const float*)d_in[12]; const float* b3  = (const float*)d_in[13];
    const float* W4 = (const float*)d_in[14]; const float* b4  = (const float*)d_in[15];
    float* out = (float*)d_out;

    __half *x16, *h16, *p016, *p116, *p216, *a16, *wthi, *wtlo;
    cudaGetSymbolAddress((void**)&x16,  g_x16);
    cudaGetSymbolAddress((void**)&h16,  g_h16);
    cudaGetSymbolAddress((void**)&p016, g_p016);
    cudaGetSymbolAddress((void**)&p116, g_p116);
    cudaGetSymbolAddress((void**)&p216, g_p216);
    cudaGetSymbolAddress((void**)&a16,  g_a16);
    cudaGetSymbolAddress((void**)&wthi, g_wthi);
    cudaGetSymbolAddress((void**)&wtlo, g_wtlo);

    // weight offsets in the pre-split arrays
    const int OW1 = 0, OT1 = 8192, OW2 = 24576, OT2 = 28672, OW3 = 45056, OW4 = 69632;

    const int EB = (N_EDGES + 255) / 256;
    const int NB = (N_NODES + 255) / 256;   // 391
    const int GB = (N_NODES + 127) / 128;   // 782
    const int PB = N_NODES / 8;             // 12500

    const int SM_C1 = 28672 + 64  * AST * 4;  // 38912
    const int SM_C2 = 28672 + 128 * AST * 4;  // 49152
    cudaFuncSetAttribute(chain_k<0, 64>,
                         cudaFuncAttributeMaxDynamicSharedMemorySize, SM_C1);
    cudaFuncSetAttribute(chain_k<128, 128>,
                         cudaFuncAttributeMaxDynamicSharedMemorySize, SM_C2);

    // fork: weights/BN/L1 on s1, graph preprocessing on stream 0
    cudaStream_t s1;
    cudaStreamCreateWithFlags(&s1, cudaStreamNonBlocking);
    cudaEvent_t e0, e1;
    cudaEventCreateWithFlags(&e0, cudaEventDisableTiming);
    cudaEventCreateWithFlags(&e1, cudaEventDisableTiming);
    cudaEventRecord(e0, 0);
    cudaStreamWaitEvent(s1, e0, 0);

    // ---- stream s1: pre-split weights, BN, L1 GEMM ----
    prepw_k<<<32, 256, 0, s1>>>(W1, wthi + OW1, wtlo + OW1, 128, 64);
    prepw_k<<<64, 256, 0, s1>>>(T1, wthi + OT1, wtlo + OT1, 256, 64);
    prepw_k<<<16, 256, 0, s1>>>(W2, wthi + OW2, wtlo + OW2, 64, 64);
    prepw_k<<<64, 256, 0, s1>>>(T2, wthi + OT2, wtlo + OT2, 256, 64);
    prepw_k<<<96, 256, 0, s1>>>(W3, wthi + OW3, wtlo + OW3, 192, 128);
    prepw_k<<<32, 256, 0, s1>>>(W4, wthi + OW4, wtlo + OW4, 128, 64);
    zero_bn_k<<<1, 128, 0, s1>>>();
    bn_stats_k<<<512, 256, 0, s1>>>(x);
    bn_final_k<<<1, 128, 0, s1>>>(gamma, beta);
    tgemm_k<128, true, true, true><<<GB, 256, 0, s1>>>(
        x, x, x, x, 128, 0, 0, 0, wthi + OW1, wtlo + OW1, b1, nullptr, h16);
    cudaEventRecord(e1, s1);

    // ---- stream 0: graph preprocessing ----
    detect_k<<<1, 256>>>((const int*)ei);
    zero_deg_k<<<NB, 256>>>();
    convert_k<<<EB, 256>>>(ei);
    dis_k<<<NB, 256>>>();
    blkred_k<<<NB, 256>>>();
    partscan_k<<<1, 512>>>(NB);
    blkscan_k<<<NB, 256>>>();
    csrfill_k<<<EB, 256>>>();

    cudaStreamWaitEvent(0, e1, 0);   // join

    // ---- TAGConv1 props + fused TAG1-GEMM + L2 -> h16 ----
    prop_k<<<PB, 256>>>((const __half2*)h16,  (__half2*)p016);
    prop_k<<<PB, 256>>>((const __half2*)p016, (__half2*)p116);
    prop_k<<<PB, 256>>>((const __half2*)p116, (__half2*)p216);
    chain_k<0, 64><<<GB, 256, SM_C1>>>(
        h16, p016, p116, p216, wthi + OT1, wtlo + OT1, t1b,
        nullptr, wthi + OW2, wtlo + OW2, b2, h16);

    // ---- TAGConv2 props + fused TAG2-GEMM + L3 -> a16 ----
    prop_k<<<PB, 256>>>((const __half2*)h16,  (__half2*)p016);
    prop_k<<<PB, 256>>>((const __half2*)p016, (__half2*)p116);
    prop_k<<<PB, 256>>>((const __half2*)p116, (__half2*)p216);
    chain_k<128, 128><<<GB, 256, SM_C2>>>(
        h16, p016, p116, p216, wthi + OT2, wtlo + OT2, t2b,
        x16, wthi + OW3, wtlo + OW3, b3, a16);

    // ---- layer 4: out = a @ W4 + b4 (fp32 out) ----
    tgemm_k<128, false, false, false><<<GB, 256>>>(
        a16, a16, a16, a16, 128, 0, 0, 1, wthi + OW4, wtlo + OW4, b4, out, nullptr);
}

// round 8
// speedup vs baseline: 2.9784x; 1.1793x over previous
#include <cuda_runtime.h>
#include <cuda_fp16.h>
#include <math.h>
#include <stdint.h>

#define N_NODES 100000
#define N_EDGES 1000000
#define AST 40   // A/W tile half stride (ldmatrix conflict-free, 16B-aligned rows)
#define CST 72   // Cs half stride

// ---------------- device scratch ----------------
__device__ int   g_is64;
__device__ __align__(16) int   g_src[N_EDGES];
__device__ __align__(16) int   g_dst[N_EDGES];
__device__ __align__(16) int   g_degi[N_NODES];
__device__ __align__(16) float g_dis[N_NODES];
__device__ __align__(16) int   g_rowptr[N_NODES + 1];
__device__ __align__(16) int   g_fill[N_NODES];
__device__ __align__(16) int2  g_cw[N_EDGES];
__device__ __align__(16) int   g_part[512];
__device__ __align__(16) float g_bnsum[128];
__device__ __align__(16) float g_bnsq[128];
__device__ __align__(16) float g_bns[128];
__device__ __align__(16) float g_bnt[128];
__device__ __align__(16) __half g_x16[N_NODES * 128];
__device__ __align__(16) __half g_a16[N_NODES * 128];
// unified activation buffer: cols [0,64)=h [64,128)=Ah [128,192)=A2h [192,256)=A3h
__device__ __align__(16) __half g_act[N_NODES * 256];
// pre-split transposed weights: hi/lo fp16, [N][K] k-major
__device__ __align__(16) __half g_wthi[77824];
__device__ __align__(16) __half g_wtlo[77824];

// ---------------- helpers ----------------
__device__ __forceinline__ float gelu_f(float v) {
    return 0.5f * v * (1.0f + erff(v * 0.70710678118654752440f));
}

__device__ __forceinline__ void mmaf16(float d[4], const uint32_t a[4],
                                       uint32_t b0, uint32_t b1) {
    asm volatile(
        "mma.sync.aligned.m16n8k16.row.col.f32.f16.f16.f32 "
        "{%0,%1,%2,%3}, {%4,%5,%6,%7}, {%8,%9}, {%0,%1,%2,%3};"
        : "+f"(d[0]), "+f"(d[1]), "+f"(d[2]), "+f"(d[3])
        : "r"(a[0]), "r"(a[1]), "r"(a[2]), "r"(a[3]), "r"(b0), "r"(b1));
}

__device__ __forceinline__ void ldsm_x4(uint32_t r[4], uint32_t a) {
    asm volatile("ldmatrix.sync.aligned.m8n8.x4.shared.b16 {%0,%1,%2,%3}, [%4];"
        : "=r"(r[0]), "=r"(r[1]), "=r"(r[2]), "=r"(r[3]) : "r"(a));
}

__device__ __forceinline__ uint32_t smaddr(const void* p) {
    return (uint32_t)__cvta_generic_to_shared(p);
}

__device__ __forceinline__ void cpa16(uint32_t dst, const void* src, bool p) {
    int sz = p ? 16 : 0;
    asm volatile("cp.async.cg.shared.global [%0], [%1], 16, %2;"
        :: "r"(dst), "l"(src), "r"(sz));
}
__device__ __forceinline__ void cpcommit() { asm volatile("cp.async.commit_group;"); }
__device__ __forceinline__ void cpwait1()  { asm volatile("cp.async.wait_group 1;"); }
__device__ __forceinline__ void cpwait0()  { asm volatile("cp.async.wait_group 0;"); }

// one 32-K step of mma with ldmatrix fragments
template <int NT>
__device__ __forceinline__ void mma_tile_l(
    float d[2][NT][4], uint32_t Ab_addr, int astr,
    uint32_t Wh_addr, uint32_t Wl_addr,
    int Rm, int Cn, int lane) {
#pragma unroll
    for (int ks = 0; ks < 2; ks++) {
        int kk = ks * 16;
        uint32_t a[2][4];
#pragma unroll
        for (int mt = 0; mt < 2; mt++) {
            int row = Rm + 16 * mt + (lane & 15);
            int kof = kk + 8 * (lane >> 4);
            ldsm_x4(a[mt], Ab_addr + ((row * astr + kof) << 1));
        }
        uint32_t bh[NT / 2][4], bl[NT / 2][4];
#pragma unroll
        for (int q = 0; q < NT / 2; q++) {
            int row = Cn + q * 16 + (lane & 7) + ((lane >> 4) << 3);
            int kof = kk + 8 * ((lane >> 3) & 1);
            uint32_t off = (uint32_t)((row * AST + kof) << 1);
            ldsm_x4(bh[q], Wh_addr + off);
            ldsm_x4(bl[q], Wl_addr + off);
        }
#pragma unroll
        for (int q = 0; q < NT / 2; q++) {
#pragma unroll
            for (int h = 0; h < 2; h++) {
                int nt = q * 2 + h;
#pragma unroll
                for (int mt = 0; mt < 2; mt++) {
                    mmaf16(d[mt][nt], a[mt], bh[q][2 * h], bh[q][2 * h + 1]);
                    mmaf16(d[mt][nt], a[mt], bl[q][2 * h], bl[q][2 * h + 1]);
                }
            }
        }
    }
}

// A tile cp.async: 128 rows x 32 halfs from contiguous fp16 [.][KX]
__device__ __forceinline__ void loadA_cp(uint32_t asbuf, const __half* Ag,
                                         int m0, int KX, int k0, int tid) {
#pragma unroll
    for (int i = 0; i < 2; i++) {
        int idx = i * 256 + tid;
        int r = idx >> 2;
        int c8 = (idx & 3) * 8;
        int gr = m0 + r;
        bool p = gr < N_NODES;
        int rr = p ? gr : (N_NODES - 1);
        cpa16(asbuf + r * (AST * 2) + c8 * 2,
              Ag + (size_t)rr * KX + k0 + c8, p);
    }
}

// W tile cp.async: N2 rows x 32 halfs (hi+lo) from [N2][Kfull]
template <int N2>
__device__ __forceinline__ void loadW_cp(uint32_t wh, uint32_t wl,
                                         const __half* Whg, const __half* Wlg,
                                         int Kfull, int k0, int tid) {
#pragma unroll
    for (int i = 0; i < N2 / 64; i++) {
        int idx = i * 256 + tid;
        int r = idx >> 2;
        int c8 = (idx & 3) * 8;
        uint32_t off = (uint32_t)(r * (AST * 2) + c8 * 2);
        cpa16(wh + off, Whg + (size_t)r * Kfull + k0 + c8, true);
        cpa16(wl + off, Wlg + (size_t)r * Kfull + k0 + c8, true);
    }
}

// double-buffered GEMM core: KX halfs from global contiguous A, then KC from Cs smem
template <int NT>
__device__ __forceinline__ void dbgemm(
    float d[2][NT][4],
    const __half* __restrict__ Ag, int m0, int KX,
    uint32_t cs_addr, int KC,
    const __half* __restrict__ Whg, const __half* __restrict__ Wlg,
    const uint32_t asb[2], const uint32_t whb[2], const uint32_t wlb[2],
    int tid, int lane, int Rm, int Cn) {
    const int Kfull = KX + KC;
    const int NTILES = Kfull / 32;
    // prologue
    if (KX > 0) loadA_cp(asb[0], Ag, m0, KX, 0, tid);
    loadW_cp<NT * 16>(whb[0], wlb[0], Whg, Wlg, Kfull, 0, tid);
    cpcommit();
    for (int t = 0; t < NTILES; t++) {
        if (t + 1 < NTILES) {
            int k1 = (t + 1) * 32;
            int nb = (t + 1) & 1;
            if (k1 < KX) loadA_cp(asb[nb], Ag, m0, KX, k1, tid);
            loadW_cp<NT * 16>(whb[nb], wlb[nb], Whg, Wlg, Kfull, k1, tid);
            cpcommit();
            cpwait1();
        } else {
            cpwait0();
        }
        __syncthreads();
        int k0 = t * 32;
        uint32_t Aaddr;
        int astr;
        if (k0 < KX) { Aaddr = asb[t & 1]; astr = AST; }
        else         { Aaddr = cs_addr + ((k0 - KX) << 1); astr = CST; }
        mma_tile_l<NT>(d, Aaddr, astr, whb[t & 1], wlb[t & 1], Rm, Cn, lane);
        __syncthreads();
    }
}

// ---------------- preprocessing ----------------
__global__ void detect_k(const int* __restrict__ ei) {
    __shared__ int anynz;
    if (threadIdx.x == 0) anynz = 0;
    __syncthreads();
    if (ei[threadIdx.x * 2 + 1] != 0) anynz = 1;
    __syncthreads();
    if (threadIdx.x == 0) g_is64 = (anynz == 0) ? 1 : 0;
}

__global__ void zero_deg_k() {
    int i = blockIdx.x * blockDim.x + threadIdx.x;
    if (i < N_NODES) g_degi[i] = 0;
}

__global__ void zero_bn_k() {
    g_bnsum[threadIdx.x] = 0.f;
    g_bnsq[threadIdx.x]  = 0.f;
}

__global__ void prepw_k(const float* __restrict__ src,
                        __half* __restrict__ dhi, __half* __restrict__ dlo,
                        int K, int N) {
    int idx = blockIdx.x * 256 + threadIdx.x;
    if (idx >= K * N) return;
    int k = idx / N, n = idx - k * N;
    float w = src[idx];
    __half h = __float2half_rn(w);
    dhi[(size_t)n * K + k] = h;
    dlo[(size_t)n * K + k] = __float2half_rn(w - __half2float(h));
}

__global__ void convert_k(const void* __restrict__ ei) {
    int e = blockIdx.x * blockDim.x + threadIdx.x;
    if (e >= N_EDGES) return;
    int s, d;
    if (g_is64) {
        const long long* p = (const long long*)ei;
        s = (int)p[e];
        d = (int)p[N_EDGES + e];
    } else {
        const int* p = (const int*)ei;
        s = p[e];
        d = p[N_EDGES + e];
    }
    g_src[e] = s;
    g_dst[e] = d;
    atomicAdd(&g_degi[d], 1);
}

__global__ void dis_k() {
    int i = blockIdx.x * blockDim.x + threadIdx.x;
    if (i >= N_NODES) return;
    int d = g_degi[i];
    g_dis[i] = (d > 0) ? rsqrtf((float)d) : 0.f;
}

__global__ void blkred_k() {
    __shared__ int ws[8];
    int i = blockIdx.x * 256 + threadIdx.x;
    int v = (i < N_NODES) ? g_degi[i] : 0;
#pragma unroll
    for (int o = 16; o; o >>= 1) v += __shfl_down_sync(0xffffffffu, v, o);
    if ((threadIdx.x & 31) == 0) ws[threadIdx.x >> 5] = v;
    __syncthreads();
    if (threadIdx.x < 8) {
        int t = ws[threadIdx.x];
#pragma unroll
        for (int o = 4; o; o >>= 1) t += __shfl_down_sync(0xffu, t, o);
        if (threadIdx.x == 0) g_part[blockIdx.x] = t;
    }
}

__global__ void partscan_k(int nb) {
    __shared__ int ws[16];
    int t = threadIdx.x, lane = t & 31, w = t >> 5;
    int v = (t < nb) ? g_part[t] : 0;
    int x = v;
#pragma unroll
    for (int o = 1; o < 32; o <<= 1) {
        int y = __shfl_up_sync(0xffffffffu, x, o);
        if (lane >= o) x += y;
    }
    if (lane == 31) ws[w] = x;
    __syncthreads();
    if (w == 0 && lane < 16) {
        int s = ws[lane];
#pragma unroll
        for (int o = 1; o < 16; o <<= 1) {
            int y = __shfl_up_sync(0x0000ffffu, s, o);
            if (lane >= o) s += y;
        }
        ws[lane] = s;
    }
    __syncthreads();
    int pre = (w ? ws[w - 1] : 0) + x - v;
    if (t < nb) g_part[t] = pre;
    if (t == nb - 1) g_rowptr[N_NODES] = pre + v;
}

__global__ void blkscan_k() {
    __shared__ int ws[8];
    int t = threadIdx.x, lane = t & 31, w = t >> 5;
    int i = blockIdx.x * 256 + t;
    int v = (i < N_NODES) ? g_degi[i] : 0;
    int x = v;
#pragma unroll
    for (int o = 1; o < 32; o <<= 1) {
        int y = __shfl_up_sync(0xffffffffu, x, o);
        if (lane >= o) x += y;
    }
    if (lane == 31) ws[w] = x;
    __syncthreads();
    if (w == 0 && lane < 8) {
        int s = ws[lane];
#pragma unroll
        for (int o = 1; o < 8; o <<= 1) {
            int y = __shfl_up_sync(0x000000ffu, s, o);
            if (lane >= o) s += y;
        }
        ws[lane] = s;
    }
    __syncthreads();
    int ex = g_part[blockIdx.x] + (w ? ws[w - 1] : 0) + x - v;
    if (i < N_NODES) { g_rowptr[i] = ex; g_fill[i] = ex; }
}

__global__ void csrfill_k() {
    int e = blockIdx.x * blockDim.x + threadIdx.x;
    if (e >= N_EDGES) return;
    int s = g_src[e], d = g_dst[e];
    int pos = atomicAdd(&g_fill[d], 1);
    g_cw[pos] = make_int2(s, __float_as_int(g_dis[s] * g_dis[d]));
}

__global__ void bn_stats_k(const float* __restrict__ x) {
    int col = threadIdx.x & 127;
    int r = blockIdx.x * 2 + (threadIdx.x >> 7);
    float s = 0.f, q = 0.f;
    for (; r < N_NODES; r += gridDim.x * 2) {
        float v = x[(size_t)r * 128 + col];
        g_x16[(size_t)r * 128 + col] = __float2half_rn(v);
        s += v;
        q += v * v;
    }
    atomicAdd(&g_bnsum[col], s);
    atomicAdd(&g_bnsq[col], q);
}

__global__ void bn_final_k(const float* __restrict__ gamma, const float* __restrict__ beta) {
    int c = threadIdx.x;
    float mean = g_bnsum[c] * (1.0f / N_NODES);
    float var  = g_bnsq[c] * (1.0f / N_NODES) - mean * mean;
    float s = gamma[c] * rsqrtf(var + 1e-5f);
    g_bns[c] = s;
    g_bnt[c] = beta[c] - mean * s;
}

// CSR propagation on g_act segments: 2 nodes per warp, 16 lanes x uint2 per row,
// unroll 4 with predicated tails. Row stride = 256 halfs.
__global__ void __launch_bounds__(256) prop_k(const __half* __restrict__ in,
                                              __half* __restrict__ out) {
    int w = blockIdx.x * 8 + (threadIdx.x >> 5);
    int lane = threadIdx.x & 31;
    int node = (w << 1) + (lane >> 4);
    int li = lane & 15;
    int beg = g_rowptr[node], end = g_rowptr[node + 1];
    float a0 = 0.f, a1 = 0.f, a2 = 0.f, a3 = 0.f;
    int e = beg;
    while (__any_sync(0xffffffffu, e < end)) {
#pragma unroll
        for (int u = 0; u < 4; u++) {
            int ee = min(e + u, N_EDGES - 1);
            int2 c = __ldg(g_cw + ee);
            float wv = (e + u < end) ? __int_as_float(c.y) : 0.f;
            uint2 r = __ldg((const uint2*)(in + (size_t)c.x * 256) + li);
            float2 f0 = __half22float2(*(__half2*)&r.x);
            float2 f1 = __half22float2(*(__half2*)&r.y);
            a0 = fmaf(wv, f0.x, a0);
            a1 = fmaf(wv, f0.y, a1);
            a2 = fmaf(wv, f1.x, a2);
            a3 = fmaf(wv, f1.y, a3);
        }
        e += 4;
    }
    __half2 o0 = __floats2half2_rn(a0, a1);
    __half2 o1 = __floats2half2_rn(a2, a3);
    uint2 uo = make_uint2(*(uint32_t*)&o0, *(uint32_t*)&o1);
    *((uint2*)(out + (size_t)node * 256) + li) = uo;
}

// ---------------- L1 GEMM: h = gelu(BN(x) @ W1 + b1) -> g_act seg0 ----------------
__global__ void __launch_bounds__(256) tgemm_bn_k(
    const float* __restrict__ x,
    const __half* __restrict__ Whg, const __half* __restrict__ Wlg,
    const float* __restrict__ bias, __half* __restrict__ Cact) {
    __shared__ __half As[128][AST];
    __shared__ __half Wh[64][AST];
    __shared__ __half Wl[64][AST];

    int tid = threadIdx.x;
    int lane = tid & 31, wid = tid >> 5;
    int gid = lane >> 2, tg = lane & 3;
    int warp_m = wid & 3, warp_n = wid >> 2;
    int Rm = warp_m * 32;
    int Cn = warp_n * 32;
    int m0 = blockIdx.x * 128;

    uint32_t as_a = smaddr(&As[0][0]);
    uint32_t wh_a = smaddr(&Wh[0][0]);
    uint32_t wl_a = smaddr(&Wl[0][0]);

    float d[2][4][4];
#pragma unroll
    for (int mt = 0; mt < 2; mt++)
#pragma unroll
        for (int nt = 0; nt < 4; nt++)
#pragma unroll
            for (int q = 0; q < 4; q++) d[mt][nt][q] = 0.f;

    for (int k0 = 0; k0 < 128; k0 += 32) {
        // A tile with fused BN -> fp16
#pragma unroll
        for (int pass = 0; pass < 4; pass++) {
            int r  = pass * 32 + (tid >> 3);
            int c4 = (tid & 7) * 4;
            int gr = m0 + r;
            uint2 u = make_uint2(0u, 0u);
            if (gr < N_NODES) {
                float4 v = *(const float4*)(x + (size_t)gr * 128 + k0 + c4);
                int kc = k0 + c4;
                v.x = v.x * g_bns[kc]     + g_bnt[kc];
                v.y = v.y * g_bns[kc + 1] + g_bnt[kc + 1];
                v.z = v.z * g_bns[kc + 2] + g_bnt[kc + 2];
                v.w = v.w * g_bns[kc + 3] + g_bnt[kc + 3];
                __half2 h01 = __floats2half2_rn(v.x, v.y);
                __half2 h23 = __floats2half2_rn(v.z, v.w);
                u.x = *(uint32_t*)&h01;
                u.y = *(uint32_t*)&h23;
            }
            *(uint2*)&As[r][c4] = u;
        }
        // W tile copy
        {
            int r = tid >> 2;
            int c8 = (tid & 3) * 8;
            *(uint4*)&Wh[r][c8] = *(const uint4*)(Whg + (size_t)r * 128 + k0 + c8);
            *(uint4*)&Wl[r][c8] = *(const uint4*)(Wlg + (size_t)r * 128 + k0 + c8);
        }
        __syncthreads();
        mma_tile_l<4>(d, as_a, AST, wh_a, wl_a, Rm, Cn, lane);
        __syncthreads();
    }

#pragma unroll
    for (int mt = 0; mt < 2; mt++) {
#pragma unroll
        for (int nt = 0; nt < 4; nt++) {
            int col = Cn + nt * 8 + tg * 2;
            float bx = bias[col], by = bias[col + 1];
            int r0 = m0 + Rm + mt * 16 + gid;
            int r1 = r0 + 8;
            float v0 = gelu_f(d[mt][nt][0] + bx), v1 = gelu_f(d[mt][nt][1] + by);
            float v2 = gelu_f(d[mt][nt][2] + bx), v3 = gelu_f(d[mt][nt][3] + by);
            if (r0 < N_NODES)
                *(__half2*)(Cact + (size_t)r0 * 256 + col) = __floats2half2_rn(v0, v1);
            if (r1 < N_NODES)
                *(__half2*)(Cact + (size_t)r1 * 256 + col) = __floats2half2_rn(v2, v3);
        }
    }
}

// ---------------- fused 2-stage chain GEMM (double-buffered cp.async) ------------
// stage1: Cs = gelu(g_act[128 rows][256] @ Wa + ba), N=64 (smem)
// stage2: out = gelu(concat(xg[XW], Cs) @ Wb + bb), N2 -> fp16 global stride OS
template <int XW, int N2, int OS>
__global__ void __launch_bounds__(256) chain_k(
    const __half* __restrict__ act,
    const __half* __restrict__ Wahg, const __half* __restrict__ Walg,
    const float* __restrict__ ba,
    const __half* __restrict__ xg,
    const __half* __restrict__ Wbhg, const __half* __restrict__ Wblg,
    const float* __restrict__ bb,
    __half* __restrict__ C16) {
    constexpr int NW = (N2 > 64) ? N2 : 64;
    extern __shared__ char sm[];
    // layout: As0 As1 | Cs | Wh0 Wl0 Wh1 Wl1
    uint32_t sbase = smaddr(sm);
    uint32_t asb[2] = { sbase, sbase + 10240 };
    uint32_t cs_a   = sbase + 20480;
    uint32_t whb[2] = { sbase + 38912, sbase + 38912 + 2u * NW * AST * 2 };
    uint32_t wlb[2] = { sbase + 38912 + 1u * NW * AST * 2,
                        sbase + 38912 + 3u * NW * AST * 2 };
    __half (*Cs)[CST] = (__half(*)[CST])(sm + 20480);

    int tid = threadIdx.x;
    int lane = tid & 31, wid = tid >> 5;
    int gid = lane >> 2, tg = lane & 3;
    int warp_m = wid & 3, warp_n = wid >> 2;
    int Rm = warp_m * 32;
    int m0 = blockIdx.x * 128;

    // -------- stage 1: K=256 from g_act, N=64 --------
    {
        int Cn = warp_n * 32;
        float d[2][4][4];
#pragma unroll
        for (int mt = 0; mt < 2; mt++)
#pragma unroll
            for (int nt = 0; nt < 4; nt++)
#pragma unroll
                for (int q = 0; q < 4; q++) d[mt][nt][q] = 0.f;

        dbgemm<4>(d, act, m0, 256, 0u, 0, Wahg, Walg, asb, whb, wlb,
                  tid, lane, Rm, Cn);

#pragma unroll
        for (int mt = 0; mt < 2; mt++) {
#pragma unroll
            for (int nt = 0; nt < 4; nt++) {
                int col = Cn + nt * 8 + tg * 2;
                float bx = ba[col], by = ba[col + 1];
                int r0 = Rm + mt * 16 + gid;
                *(__half2*)&Cs[r0][col] =
                    __floats2half2_rn(gelu_f(d[mt][nt][0] + bx), gelu_f(d[mt][nt][1] + by));
                *(__half2*)&Cs[r0 + 8][col] =
                    __floats2half2_rn(gelu_f(d[mt][nt][2] + bx), gelu_f(d[mt][nt][3] + by));
            }
        }
    }
    __syncthreads();

    // -------- stage 2: K = XW (global) + 64 (Cs), N = N2 --------
    {
        constexpr int NT = N2 / 16;
        int Cn = warp_n * (N2 / 2);
        float d[2][NT][4];
#pragma unroll
        for (int mt = 0; mt < 2; mt++)
#pragma unroll
            for (int nt = 0; nt < NT; nt++)
#pragma unroll
                for (int q = 0; q < 4; q++) d[mt][nt][q] = 0.f;

        dbgemm<NT>(d, xg, m0, XW, cs_a, 64, Wbhg, Wblg, asb, whb, wlb,
                   tid, lane, Rm, Cn);

#pragma unroll
        for (int mt = 0; mt < 2; mt++) {
#pragma unroll
            for (int nt = 0; nt < NT; nt++) {
                int col = Cn + nt * 8 + tg * 2;
                float bx = bb[col], by = bb[col + 1];
                int r0 = m0 + Rm + mt * 16 + gid;
                int r1 = r0 + 8;
                float v0 = gelu_f(d[mt][nt][0] + bx), v1 = gelu_f(d[mt][nt][1] + by);
                float v2 = gelu_f(d[mt][nt][2] + bx), v3 = gelu_f(d[mt][nt][3] + by);
                if (r0 < N_NODES)
                    *(__half2*)(C16 + (size_t)r0 * OS + col) = __floats2half2_rn(v0, v1);
                if (r1 < N_NODES)
                    *(__half2*)(C16 + (size_t)r1 * OS + col) = __floats2half2_rn(v2, v3);
            }
        }
    }
}

// ---------------- L4 GEMM: out = a16 @ W4 + b4 (fp32 out) ----------------
__global__ void __launch_bounds__(256) tgemm16_k(
    const __half* __restrict__ Ag,
    const __half* __restrict__ Whg, const __half* __restrict__ Wlg,
    const float* __restrict__ bias, float* __restrict__ C) {
    __shared__ __half As[2][128][AST];
    __shared__ __half Wh[2][64][AST];
    __shared__ __half Wl[2][64][AST];

    int tid = threadIdx.x;
    int lane = tid & 31, wid = tid >> 5;
    int gid = lane >> 2, tg = lane & 3;
    int warp_m = wid & 3, warp_n = wid >> 2;
    int Rm = warp_m * 32;
    int Cn = warp_n * 32;
    int m0 = blockIdx.x * 128;

    uint32_t asb[2] = { smaddr(&As[0][0][0]), smaddr(&As[1][0][0]) };
    uint32_t whb[2] = { smaddr(&Wh[0][0][0]), smaddr(&Wh[1][0][0]) };
    uint32_t wlb[2] = { smaddr(&Wl[0][0][0]), smaddr(&Wl[1][0][0]) };

    float d[2][4][4];
#pragma unroll
    for (int mt = 0; mt < 2; mt++)
#pragma unroll
        for (int nt = 0; nt < 4; nt++)
#pragma unroll
            for (int q = 0; q < 4; q++) d[mt][nt][q] = 0.f;

    dbgemm<4>(d, Ag, m0, 128, 0u, 0, Whg, Wlg, asb, whb, wlb,
              tid, lane, Rm, Cn);

#pragma unroll
    for (int mt = 0; mt < 2; mt++) {
#pragma unroll
        for (int nt = 0; nt < 4; nt++) {
            int col = Cn + nt * 8 + tg * 2;
            float bx = bias[col], by = bias[col + 1];
            int r0 = m0 + Rm + mt * 16 + gid;
            int r1 = r0 + 8;
            if (r0 < N_NODES)
                *(float2*)(C + (size_t)r0 * 64 + col) =
                    make_float2(d[mt][nt][0] + bx, d[mt][nt][1] + by);
            if (r1 < N_NODES)
                *(float2*)(C + (size_t)r1 * 64 + col) =
                    make_float2(d[mt][nt][2] + bx, d[mt][nt][3] + by);
        }
    }
}

// ---------------- host launcher ----------------
extern "C" void kernel_launch(void* const* d_in, const int* in_sizes, int n_in,
                              void* d_out, int out_size) {
    const float* x     = (const float*)d_in[0];
    const void*  ei    = d_in[1];
    const float* gamma = (const float*)d_in[2];
    const float* beta  = (const float*)d_in[3];
    const float* W1 = (const float*)d_in[4];  const float* b1  = (const float*)d_in[5];
    const float* T1 = (const float*)d_in[6];  const float* t1b = (const float*)d_in[7];
    const float* W2 = (const float*)d_in[8];  const float* b2  = (const float*)d_in[9];
    const float* T2 = (const float*)d_in[10]; const float* t2b = (const float*)d_in[11];
    const float* W3 = (const float*)d_in[12]; const float* b3  = (const float*)d_in[13];
    const float* W4 = (const float*)d_in[14]; const float* b4  = (const float*)d_in[15];
    float* out = (float*)d_out;

    __half *x16, *a16, *act, *wthi, *wtlo;
    cudaGetSymbolAddress((void**)&x16,  g_x16);
    cudaGetSymbolAddress((void**)&a16,  g_a16);
    cudaGetSymbolAddress((void**)&act,  g_act);
    cudaGetSymbolAddress((void**)&wthi, g_wthi);
    cudaGetSymbolAddress((void**)&wtlo, g_wtlo);

    const int OW1 = 0, OT1 = 8192, OW2 = 24576, OT2 = 28672, OW3 = 45056, OW4 = 69632;

    const int EB = (N_EDGES + 255) / 256;
    const int NB = (N_NODES + 255) / 256;   // 391
    const int GB = (N_NODES + 127) / 128;   // 782
    const int PB = N_NODES / 16;            // 6250 (2 nodes/warp, 8 warps/block)

    const int SM_C1 = 38912 + 64  * AST * 2 * 4;  // 59392
    const int SM_C2 = 38912 + 128 * AST * 2 * 4;  // 79872
    cudaFuncSetAttribute(chain_k<0, 64, 256>,
                         cudaFuncAttributeMaxDynamicSharedMemorySize, SM_C1);
    cudaFuncSetAttribute(chain_k<128, 128, 128>,
                         cudaFuncAttributeMaxDynamicSharedMemorySize, SM_C2);

    // fork: weights/BN/L1 on s1, graph preprocessing on stream 0
    cudaStream_t s1;
    cudaStreamCreateWithFlags(&s1, cudaStreamNonBlocking);
    cudaEvent_t e0, e1;
    cudaEventCreateWithFlags(&e0, cudaEventDisableTiming);
    cudaEventCreateWithFlags(&e1, cudaEventDisableTiming);
    cudaEventRecord(e0, 0);
    cudaStreamWaitEvent(s1, e0, 0);

    // ---- stream s1: pre-split weights, BN, L1 GEMM ----
    prepw_k<<<32, 256, 0, s1>>>(W1, wthi + OW1, wtlo + OW1, 128, 64);
    prepw_k<<<64, 256, 0, s1>>>(T1, wthi + OT1, wtlo + OT1, 256, 64);
    prepw_k<<<16, 256, 0, s1>>>(W2, wthi + OW2, wtlo + OW2, 64, 64);
    prepw_k<<<64, 256, 0, s1>>>(T2, wthi + OT2, wtlo + OT2, 256, 64);
    prepw_k<<<96, 256, 0, s1>>>(W3, wthi + OW3, wtlo + OW3, 192, 128);
    prepw_k<<<32, 256, 0, s1>>>(W4, wthi + OW4, wtlo + OW4, 128, 64);
    zero_bn_k<<<1, 128, 0, s1>>>();
    bn_stats_k<<<512, 256, 0, s1>>>(x);
    bn_final_k<<<1, 128, 0, s1>>>(gamma, beta);
    tgemm_bn_k<<<GB, 256, 0, s1>>>(x, wthi + OW1, wtlo + OW1, b1, act);
    cudaEventRecord(e1, s1);

    // ---- stream 0: graph preprocessing ----
    detect_k<<<1, 256>>>((const int*)ei);
    zero_deg_k<<<NB, 256>>>();
    convert_k<<<EB, 256>>>(ei);
    dis_k<<<NB, 256>>>();
    blkred_k<<<NB, 256>>>();
    partscan_k<<<1, 512>>>(NB);
    blkscan_k<<<NB, 256>>>();
    csrfill_k<<<EB, 256>>>();

    cudaStreamWaitEvent(0, e1, 0);   // join

    // ---- TAGConv1: props fill segs 1..3, then chain (TAG1 + L2) -> h in seg0 ----
    prop_k<<<PB, 256>>>(act,       act + 64);
    prop_k<<<PB, 256>>>(act + 64,  act + 128);
    prop_k<<<PB, 256>>>(act + 128, act + 192);
    chain_k<0, 64, 256><<<GB, 256, SM_C1>>>(
        act, wthi + OT1, wtlo + OT1, t1b,
        nullptr, wthi + OW2, wtlo + OW2, b2, act);

    // ---- TAGConv2: same, then chain (TAG2 + L3 concat x) -> a16 ----
    prop_k<<<PB, 256>>>(act,       act + 64);
    prop_k<<<PB, 256>>>(act + 64,  act + 128);
    prop_k<<<PB, 256>>>(act + 128, act + 192);
    chain_k<128, 128, 128><<<GB, 256, SM_C2>>>(
        act, wthi + OT2, wtlo + OT2, t2b,
        x16, wthi + OW3, wtlo + OW3, b3, a16);

    // ---- layer 4 ----
    tgemm16_k<<<GB, 256>>>(a16, wthi + OW4, wtlo + OW4, b4, out);
}

// round 9
// speedup vs baseline: 3.2385x; 1.0873x over previous
#include <cuda_runtime.h>
#include <cuda_fp16.h>
#include <math.h>
#include <stdint.h>

#define N_NODES 100000
#define N_EDGES 1000000
#define AST 40   // A/W tile half stride (ldmatrix conflict-free, 16B-aligned rows)
#define CST 72   // Cs half stride

// ---------------- device scratch ----------------
__device__ int   g_is64;
__device__ __align__(16) int   g_degi[N_NODES];
__device__ __align__(16) float g_dis[N_NODES];
__device__ __align__(16) int   g_rowptr[N_NODES + 1];
__device__ __align__(16) int   g_fill[N_NODES];
__device__ __align__(16) int2  g_cw[N_EDGES];
__device__ __align__(16) int   g_part[512];
__device__ __align__(16) float g_bnsum[128];
__device__ __align__(16) float g_bnsq[128];
__device__ __align__(16) float g_bns[128];
__device__ __align__(16) float g_bnt[128];
__device__ __align__(16) __half g_x16[N_NODES * 128];
__device__ __align__(16) __half g_a16[N_NODES * 128];
// unified activation buffer: cols [0,64)=h [64,128)=Ah [128,192)=A2h [192,256)=A3h
__device__ __align__(16) __half g_act[N_NODES * 256];
// pre-split transposed weights: hi/lo fp16, [N][K] k-major
__device__ __align__(16) __half g_wthi[77824];
__device__ __align__(16) __half g_wtlo[77824];

// ---------------- helpers ----------------
__device__ __forceinline__ float gelu_f(float v) {
    return 0.5f * v * (1.0f + erff(v * 0.70710678118654752440f));
}

__device__ __forceinline__ void mmaf16(float d[4], const uint32_t a[4],
                                       uint32_t b0, uint32_t b1) {
    asm volatile(
        "mma.sync.aligned.m16n8k16.row.col.f32.f16.f16.f32 "
        "{%0,%1,%2,%3}, {%4,%5,%6,%7}, {%8,%9}, {%0,%1,%2,%3};"
        : "+f"(d[0]), "+f"(d[1]), "+f"(d[2]), "+f"(d[3])
        : "r"(a[0]), "r"(a[1]), "r"(a[2]), "r"(a[3]), "r"(b0), "r"(b1));
}

__device__ __forceinline__ void ldsm_x4(uint32_t r[4], uint32_t a) {
    asm volatile("ldmatrix.sync.aligned.m8n8.x4.shared.b16 {%0,%1,%2,%3}, [%4];"
        : "=r"(r[0]), "=r"(r[1]), "=r"(r[2]), "=r"(r[3]) : "r"(a));
}

__device__ __forceinline__ uint32_t smaddr(const void* p) {
    return (uint32_t)__cvta_generic_to_shared(p);
}

__device__ __forceinline__ void cpa16(uint32_t dst, const void* src, bool p) {
    int sz = p ? 16 : 0;
    asm volatile("cp.async.cg.shared.global [%0], [%1], 16, %2;"
        :: "r"(dst), "l"(src), "r"(sz));
}
__device__ __forceinline__ void cpcommit() { asm volatile("cp.async.commit_group;"); }
__device__ __forceinline__ void cpwait1()  { asm volatile("cp.async.wait_group 1;"); }
__device__ __forceinline__ void cpwait0()  { asm volatile("cp.async.wait_group 0;"); }

// one 32-K step of mma with ldmatrix fragments
template <int NT>
__device__ __forceinline__ void mma_tile_l(
    float d[2][NT][4], uint32_t Ab_addr, int astr,
    uint32_t Wh_addr, uint32_t Wl_addr,
    int Rm, int Cn, int lane) {
#pragma unroll
    for (int ks = 0; ks < 2; ks++) {
        int kk = ks * 16;
        uint32_t a[2][4];
#pragma unroll
        for (int mt = 0; mt < 2; mt++) {
            int row = Rm + 16 * mt + (lane & 15);
            int kof = kk + 8 * (lane >> 4);
            ldsm_x4(a[mt], Ab_addr + ((row * astr + kof) << 1));
        }
        uint32_t bh[NT / 2][4], bl[NT / 2][4];
#pragma unroll
        for (int q = 0; q < NT / 2; q++) {
            int row = Cn + q * 16 + (lane & 7) + ((lane >> 4) << 3);
            int kof = kk + 8 * ((lane >> 3) & 1);
            uint32_t off = (uint32_t)((row * AST + kof) << 1);
            ldsm_x4(bh[q], Wh_addr + off);
            ldsm_x4(bl[q], Wl_addr + off);
        }
#pragma unroll
        for (int q = 0; q < NT / 2; q++) {
#pragma unroll
            for (int h = 0; h < 2; h++) {
                int nt = q * 2 + h;
#pragma unroll
                for (int mt = 0; mt < 2; mt++) {
                    mmaf16(d[mt][nt], a[mt], bh[q][2 * h], bh[q][2 * h + 1]);
                    mmaf16(d[mt][nt], a[mt], bl[q][2 * h], bl[q][2 * h + 1]);
                }
            }
        }
    }
}

// A tile cp.async: 128 rows x 32 halfs from contiguous fp16 [.][KX]
__device__ __forceinline__ void loadA_cp(uint32_t asbuf, const __half* Ag,
                                         int m0, int KX, int k0, int tid) {
#pragma unroll
    for (int i = 0; i < 2; i++) {
        int idx = i * 256 + tid;
        int r = idx >> 2;
        int c8 = (idx & 3) * 8;
        int gr = m0 + r;
        bool p = gr < N_NODES;
        int rr = p ? gr : (N_NODES - 1);
        cpa16(asbuf + r * (AST * 2) + c8 * 2,
              Ag + (size_t)rr * KX + k0 + c8, p);
    }
}

// W tile cp.async: N2 rows x 32 halfs (hi+lo) from [N2][Kfull]
template <int N2>
__device__ __forceinline__ void loadW_cp(uint32_t wh, uint32_t wl,
                                         const __half* Whg, const __half* Wlg,
                                         int Kfull, int k0, int tid) {
#pragma unroll
    for (int i = 0; i < N2 / 64; i++) {
        int idx = i * 256 + tid;
        int r = idx >> 2;
        int c8 = (idx & 3) * 8;
        uint32_t off = (uint32_t)(r * (AST * 2) + c8 * 2);
        cpa16(wh + off, Whg + (size_t)r * Kfull + k0 + c8, true);
        cpa16(wl + off, Wlg + (size_t)r * Kfull + k0 + c8, true);
    }
}

// double-buffered GEMM core: KX halfs from global contiguous A, then KC from Cs smem
template <int NT>
__device__ __forceinline__ void dbgemm(
    float d[2][NT][4],
    const __half* __restrict__ Ag, int m0, int KX,
    uint32_t cs_addr, int KC,
    const __half* __restrict__ Whg, const __half* __restrict__ Wlg,
    const uint32_t asb[2], const uint32_t whb[2], const uint32_t wlb[2],
    int tid, int lane, int Rm, int Cn) {
    const int Kfull = KX + KC;
    const int NTILES = Kfull / 32;
    // prologue
    if (KX > 0) loadA_cp(asb[0], Ag, m0, KX, 0, tid);
    loadW_cp<NT * 16>(whb[0], wlb[0], Whg, Wlg, Kfull, 0, tid);
    cpcommit();
    for (int t = 0; t < NTILES; t++) {
        if (t + 1 < NTILES) {
            int k1 = (t + 1) * 32;
            int nb = (t + 1) & 1;
            if (k1 < KX) loadA_cp(asb[nb], Ag, m0, KX, k1, tid);
            loadW_cp<NT * 16>(whb[nb], wlb[nb], Whg, Wlg, Kfull, k1, tid);
            cpcommit();
            cpwait1();
        } else {
            cpwait0();
        }
        __syncthreads();
        int k0 = t * 32;
        uint32_t Aaddr;
        int astr;
        if (k0 < KX) { Aaddr = asb[t & 1]; astr = AST; }
        else         { Aaddr = cs_addr + ((k0 - KX) << 1); astr = CST; }
        mma_tile_l<NT>(d, Aaddr, astr, whb[t & 1], wlb[t & 1], Rm, Cn, lane);
        __syncthreads();
    }
}

// ---------------- preprocessing ----------------
// zero degrees + (block 0) detect edge_index dtype
__global__ void zero_detect_k(const int* __restrict__ ei) {
    int i = blockIdx.x * 256 + threadIdx.x;
    if (i < N_NODES) g_degi[i] = 0;
    if (blockIdx.x == 0) {
        __shared__ int anynz;
        if (threadIdx.x == 0) anynz = 0;
        __syncthreads();
        if (ei[threadIdx.x * 2 + 1] != 0) anynz = 1;
        __syncthreads();
        if (threadIdx.x == 0) g_is64 = (anynz == 0) ? 1 : 0;
    }
}

// degree count straight from edge_index dst half
__global__ void deg_k(const void* __restrict__ ei) {
    int e = blockIdx.x * 256 + threadIdx.x;
    if (e >= N_EDGES) return;
    int d = g_is64 ? (int)((const long long*)ei)[N_EDGES + e]
                   : ((const int*)ei)[N_EDGES + e];
    atomicAdd(&g_degi[d], 1);
}

// all 6 weight matrices pre-split (src fp32 [K][N] -> hi/lo fp16 [N][K]) + BN zero
__global__ void prepw_all_k(const float* __restrict__ W1, const float* __restrict__ T1,
                            const float* __restrict__ W2, const float* __restrict__ T2,
                            const float* __restrict__ W3, const float* __restrict__ W4,
                            __half* __restrict__ hi, __half* __restrict__ lo) {
    int idx = blockIdx.x * 256 + threadIdx.x;
    if (idx >= 77824) {
        int z = idx - 77824;
        if (z < 128)      g_bnsum[z] = 0.f;
        else if (z < 256) g_bnsq[z - 128] = 0.f;
        return;
    }
    const float* src; int base, K, N;
    if (idx < 8192)       { src = W1; base = 0;     K = 128; N = 64;  }
    else if (idx < 24576) { src = T1; base = 8192;  K = 256; N = 64;  }
    else if (idx < 28672) { src = W2; base = 24576; K = 64;  N = 64;  }
    else if (idx < 45056) { src = T2; base = 28672; K = 256; N = 64;  }
    else if (idx < 69632) { src = W3; base = 45056; K = 192; N = 128; }
    else                  { src = W4; base = 69632; K = 128; N = 64;  }
    int r = idx - base;
    int k = r / N, n = r - k * N;
    float w = src[r];
    __half h = __float2half_rn(w);
    hi[base + n * K + k] = h;
    lo[base + n * K + k] = __float2half_rn(w - __half2float(h));
}

// block reduce of degrees + dis computation (fused)
__global__ void blkred_dis_k() {
    __shared__ int ws[8];
    int i = blockIdx.x * 256 + threadIdx.x;
    int v = (i < N_NODES) ? g_degi[i] : 0;
    if (i < N_NODES) g_dis[i] = (v > 0) ? rsqrtf((float)v) : 0.f;
    int s = v;
#pragma unroll
    for (int o = 16; o; o >>= 1) s += __shfl_down_sync(0xffffffffu, s, o);
    if ((threadIdx.x & 31) == 0) ws[threadIdx.x >> 5] = s;
    __syncthreads();
    if (threadIdx.x < 8) {
        int t = ws[threadIdx.x];
#pragma unroll
        for (int o = 4; o; o >>= 1) t += __shfl_down_sync(0xffu, t, o);
        if (threadIdx.x == 0) g_part[blockIdx.x] = t;
    }
}

__global__ void partscan_k(int nb) {
    __shared__ int ws[16];
    int t = threadIdx.x, lane = t & 31, w = t >> 5;
    int v = (t < nb) ? g_part[t] : 0;
    int x = v;
#pragma unroll
    for (int o = 1; o < 32; o <<= 1) {
        int y = __shfl_up_sync(0xffffffffu, x, o);
        if (lane >= o) x += y;
    }
    if (lane == 31) ws[w] = x;
    __syncthreads();
    if (w == 0 && lane < 16) {
        int s = ws[lane];
#pragma unroll
        for (int o = 1; o < 16; o <<= 1) {
            int y = __shfl_up_sync(0x0000ffffu, s, o);
            if (lane >= o) s += y;
        }
        ws[lane] = s;
    }
    __syncthreads();
    int pre = (w ? ws[w - 1] : 0) + x - v;
    if (t < nb) g_part[t] = pre;
    if (t == nb - 1) g_rowptr[N_NODES] = pre + v;
}

__global__ void blkscan_k() {
    __shared__ int ws[8];
    int t = threadIdx.x, lane = t & 31, w = t >> 5;
    int i = blockIdx.x * 256 + t;
    int v = (i < N_NODES) ? g_degi[i] : 0;
    int x = v;
#pragma unroll
    for (int o = 1; o < 32; o <<= 1) {
        int y = __shfl_up_sync(0xffffffffu, x, o);
        if (lane >= o) x += y;
    }
    if (lane == 31) ws[w] = x;
    __syncthreads();
    if (w == 0 && lane < 8) {
        int s = ws[lane];
#pragma unroll
        for (int o = 1; o < 8; o <<= 1) {
            int y = __shfl_up_sync(0x000000ffu, s, o);
            if (lane >= o) s += y;
        }
        ws[lane] = s;
    }
    __syncthreads();
    int ex = g_part[blockIdx.x] + (w ? ws[w - 1] : 0) + x - v;
    if (i < N_NODES) { g_rowptr[i] = ex; g_fill[i] = ex; }
}

// CSR fill straight from edge_index
__global__ void csrfill_k(const void* __restrict__ ei) {
    int e = blockIdx.x * 256 + threadIdx.x;
    if (e >= N_EDGES) return;
    int s, d;
    if (g_is64) {
        const long long* p = (const long long*)ei;
        s = (int)p[e];
        d = (int)p[N_EDGES + e];
    } else {
        const int* p = (const int*)ei;
        s = p[e];
        d = p[N_EDGES + e];
    }
    int pos = atomicAdd(&g_fill[d], 1);
    g_cw[pos] = make_int2(s, __float_as_int(g_dis[s] * g_dis[d]));
}

__global__ void bn_stats_k(const float* __restrict__ x) {
    int col = threadIdx.x & 127;
    int r = blockIdx.x * 2 + (threadIdx.x >> 7);
    float s = 0.f, q = 0.f;
    for (; r < N_NODES; r += gridDim.x * 2) {
        float v = x[(size_t)r * 128 + col];
        g_x16[(size_t)r * 128 + col] = __float2half_rn(v);
        s += v;
        q += v * v;
    }
    atomicAdd(&g_bnsum[col], s);
    atomicAdd(&g_bnsq[col], q);
}

__global__ void bn_final_k(const float* __restrict__ gamma, const float* __restrict__ beta) {
    int c = threadIdx.x;
    float mean = g_bnsum[c] * (1.0f / N_NODES);
    float var  = g_bnsq[c] * (1.0f / N_NODES) - mean * mean;
    float s = gamma[c] * rsqrtf(var + 1e-5f);
    g_bns[c] = s;
    g_bnt[c] = beta[c] - mean * s;
}

// CSR propagation on g_act segments: 4 nodes/warp, 8 lanes x uint4 per row.
// Row stride = 256 halfs; unroll 4 with predicated tails.
__global__ void __launch_bounds__(256) prop_k(const __half* __restrict__ in,
                                              __half* __restrict__ out) {
    int w = blockIdx.x * 8 + (threadIdx.x >> 5);
    int lane = threadIdx.x & 31;
    int node = (w << 2) + (lane >> 3);
    int li = lane & 7;
    int beg = g_rowptr[node], end = g_rowptr[node + 1];
    float a0 = 0.f, a1 = 0.f, a2 = 0.f, a3 = 0.f;
    float a4 = 0.f, a5 = 0.f, a6 = 0.f, a7 = 0.f;
    int e = beg;
    while (__any_sync(0xffffffffu, e < end)) {
#pragma unroll
        for (int u = 0; u < 4; u++) {
            int ee = min(e + u, N_EDGES - 1);
            int2 c = __ldg(g_cw + ee);
            float wv = (e + u < end) ? __int_as_float(c.y) : 0.f;
            uint4 r = __ldg((const uint4*)(in + (size_t)c.x * 256) + li);
            float2 f0 = __half22float2(*(__half2*)&r.x);
            float2 f1 = __half22float2(*(__half2*)&r.y);
            float2 f2 = __half22float2(*(__half2*)&r.z);
            float2 f3 = __half22float2(*(__half2*)&r.w);
            a0 = fmaf(wv, f0.x, a0);
            a1 = fmaf(wv, f0.y, a1);
            a2 = fmaf(wv, f1.x, a2);
            a3 = fmaf(wv, f1.y, a3);
            a4 = fmaf(wv, f2.x, a4);
            a5 = fmaf(wv, f2.y, a5);
            a6 = fmaf(wv, f3.x, a6);
            a7 = fmaf(wv, f3.y, a7);
        }
        e += 4;
    }
    __half2 o0 = __floats2half2_rn(a0, a1);
    __half2 o1 = __floats2half2_rn(a2, a3);
    __half2 o2 = __floats2half2_rn(a4, a5);
    __half2 o3 = __floats2half2_rn(a6, a7);
    uint4 uo = make_uint4(*(uint32_t*)&o0, *(uint32_t*)&o1,
                          *(uint32_t*)&o2, *(uint32_t*)&o3);
    *((uint4*)(out + (size_t)node * 256) + li) = uo;
}

// ---------------- L1 GEMM: h = gelu(BN(x) @ W1 + b1) -> g_act seg0 ----------------
__global__ void __launch_bounds__(256) tgemm_bn_k(
    const float* __restrict__ x,
    const __half* __restrict__ Whg, const __half* __restrict__ Wlg,
    const float* __restrict__ bias, __half* __restrict__ Cact) {
    __shared__ __half As[128][AST];
    __shared__ __half Wh[64][AST];
    __shared__ __half Wl[64][AST];

    int tid = threadIdx.x;
    int lane = tid & 31, wid = tid >> 5;
    int gid = lane >> 2, tg = lane & 3;
    int warp_m = wid & 3, warp_n = wid >> 2;
    int Rm = warp_m * 32;
    int Cn = warp_n * 32;
    int m0 = blockIdx.x * 128;

    uint32_t as_a = smaddr(&As[0][0]);
    uint32_t wh_a = smaddr(&Wh[0][0]);
    uint32_t wl_a = smaddr(&Wl[0][0]);

    float d[2][4][4];
#pragma unroll
    for (int mt = 0; mt < 2; mt++)
#pragma unroll
        for (int nt = 0; nt < 4; nt++)
#pragma unroll
            for (int q = 0; q < 4; q++) d[mt][nt][q] = 0.f;

    for (int k0 = 0; k0 < 128; k0 += 32) {
        // A tile with fused BN -> fp16
#pragma unroll
        for (int pass = 0; pass < 4; pass++) {
            int r  = pass * 32 + (tid >> 3);
            int c4 = (tid & 7) * 4;
            int gr = m0 + r;
            uint2 u = make_uint2(0u, 0u);
            if (gr < N_NODES) {
                float4 v = *(const float4*)(x + (size_t)gr * 128 + k0 + c4);
                int kc = k0 + c4;
                v.x = v.x * g_bns[kc]     + g_bnt[kc];
                v.y = v.y * g_bns[kc + 1] + g_bnt[kc + 1];
                v.z = v.z * g_bns[kc + 2] + g_bnt[kc + 2];
                v.w = v.w * g_bns[kc + 3] + g_bnt[kc + 3];
                __half2 h01 = __floats2half2_rn(v.x, v.y);
                __half2 h23 = __floats2half2_rn(v.z, v.w);
                u.x = *(uint32_t*)&h01;
                u.y = *(uint32_t*)&h23;
            }
            *(uint2*)&As[r][c4] = u;
        }
        // W tile copy
        {
            int r = tid >> 2;
            int c8 = (tid & 3) * 8;
            *(uint4*)&Wh[r][c8] = *(const uint4*)(Whg + (size_t)r * 128 + k0 + c8);
            *(uint4*)&Wl[r][c8] = *(const uint4*)(Wlg + (size_t)r * 128 + k0 + c8);
        }
        __syncthreads();
        mma_tile_l<4>(d, as_a, AST, wh_a, wl_a, Rm, Cn, lane);
        __syncthreads();
    }

#pragma unroll
    for (int mt = 0; mt < 2; mt++) {
#pragma unroll
        for (int nt = 0; nt < 4; nt++) {
            int col = Cn + nt * 8 + tg * 2;
            float bx = bias[col], by = bias[col + 1];
            int r0 = m0 + Rm + mt * 16 + gid;
            int r1 = r0 + 8;
            float v0 = gelu_f(d[mt][nt][0] + bx), v1 = gelu_f(d[mt][nt][1] + by);
            float v2 = gelu_f(d[mt][nt][2] + bx), v3 = gelu_f(d[mt][nt][3] + by);
            if (r0 < N_NODES)
                *(__half2*)(Cact + (size_t)r0 * 256 + col) = __floats2half2_rn(v0, v1);
            if (r1 < N_NODES)
                *(__half2*)(Cact + (size_t)r1 * 256 + col) = __floats2half2_rn(v2, v3);
        }
    }
}

// ---------------- fused 2-stage chain GEMM (double-buffered cp.async) ------------
// stage1: Cs = gelu(g_act[128 rows][256] @ Wa + ba), N=64 (smem)
// stage2: out = gelu(concat(xg[XW], Cs) @ Wb + bb), N2 -> fp16 global stride OS
template <int XW, int N2, int OS>
__global__ void __launch_bounds__(256) chain_k(
    const __half* __restrict__ act,
    const __half* __restrict__ Wahg, const __half* __restrict__ Walg,
    const float* __restrict__ ba,
    const __half* __restrict__ xg,
    const __half* __restrict__ Wbhg, const __half* __restrict__ Wblg,
    const float* __restrict__ bb,
    __half* __restrict__ C16) {
    constexpr int NW = (N2 > 64) ? N2 : 64;
    extern __shared__ char sm[];
    // layout: As0 As1 | Cs | Wh0 Wl0 Wh1 Wl1
    uint32_t sbase = smaddr(sm);
    uint32_t asb[2] = { sbase, sbase + 10240 };
    uint32_t cs_a   = sbase + 20480;
    uint32_t whb[2] = { sbase + 38912, sbase + 38912 + 2u * NW * AST * 2 };
    uint32_t wlb[2] = { sbase + 38912 + 1u * NW * AST * 2,
                        sbase + 38912 + 3u * NW * AST * 2 };
    __half (*Cs)[CST] = (__half(*)[CST])(sm + 20480);

    int tid = threadIdx.x;
    int lane = tid & 31, wid = tid >> 5;
    int gid = lane >> 2, tg = lane & 3;
    int warp_m = wid & 3, warp_n = wid >> 2;
    int Rm = warp_m * 32;
    int m0 = blockIdx.x * 128;

    // -------- stage 1: K=256 from g_act, N=64 --------
    {
        int Cn = warp_n * 32;
        float d[2][4][4];
#pragma unroll
        for (int mt = 0; mt < 2; mt++)
#pragma unroll
            for (int nt = 0; nt < 4; nt++)
#pragma unroll
                for (int q = 0; q < 4; q++) d[mt][nt][q] = 0.f;

        dbgemm<4>(d, act, m0, 256, 0u, 0, Wahg, Walg, asb, whb, wlb,
                  tid, lane, Rm, Cn);

#pragma unroll
        for (int mt = 0; mt < 2; mt++) {
#pragma unroll
            for (int nt = 0; nt < 4; nt++) {
                int col = Cn + nt * 8 + tg * 2;
                float bx = ba[col], by = ba[col + 1];
                int r0 = Rm + mt * 16 + gid;
                *(__half2*)&Cs[r0][col] =
                    __floats2half2_rn(gelu_f(d[mt][nt][0] + bx), gelu_f(d[mt][nt][1] + by));
                *(__half2*)&Cs[r0 + 8][col] =
                    __floats2half2_rn(gelu_f(d[mt][nt][2] + bx), gelu_f(d[mt][nt][3] + by));
            }
        }
    }
    __syncthreads();

    // -------- stage 2: K = XW (global) + 64 (Cs), N = N2 --------
    {
        constexpr int NT = N2 / 16;
        int Cn = warp_n * (N2 / 2);
        float d[2][NT][4];
#pragma unroll
        for (int mt = 0; mt < 2; mt++)
#pragma unroll
            for (int nt = 0; nt < NT; nt++)
#pragma unroll
                for (int q = 0; q < 4; q++) d[mt][nt][q] = 0.f;

        dbgemm<NT>(d, xg, m0, XW, cs_a, 64, Wbhg, Wblg, asb, whb, wlb,
                   tid, lane, Rm, Cn);

#pragma unroll
        for (int mt = 0; mt < 2; mt++) {
#pragma unroll
            for (int nt = 0; nt < NT; nt++) {
                int col = Cn + nt * 8 + tg * 2;
                float bx = bb[col], by = bb[col + 1];
                int r0 = m0 + Rm + mt * 16 + gid;
                int r1 = r0 + 8;
                float v0 = gelu_f(d[mt][nt][0] + bx), v1 = gelu_f(d[mt][nt][1] + by);
                float v2 = gelu_f(d[mt][nt][2] + bx), v3 = gelu_f(d[mt][nt][3] + by);
                if (r0 < N_NODES)
                    *(__half2*)(C16 + (size_t)r0 * OS + col) = __floats2half2_rn(v0, v1);
                if (r1 < N_NODES)
                    *(__half2*)(C16 + (size_t)r1 * OS + col) = __floats2half2_rn(v2, v3);
            }
        }
    }
}

// ---------------- L4 GEMM: out = a16 @ W4 + b4 (fp32 out) ----------------
__global__ void __launch_bounds__(256) tgemm16_k(
    const __half* __restrict__ Ag,
    const __half* __restrict__ Whg, const __half* __restrict__ Wlg,
    const float* __restrict__ bias, float* __restrict__ C) {
    __shared__ __half As[2][128][AST];
    __shared__ __half Wh[2][64][AST];
    __shared__ __half Wl[2][64][AST];

    int tid = threadIdx.x;
    int lane = tid & 31, wid = tid >> 5;
    int gid = lane >> 2, tg = lane & 3;
    int warp_m = wid & 3, warp_n = wid >> 2;
    int Rm = warp_m * 32;
    int Cn = warp_n * 32;
    int m0 = blockIdx.x * 128;

    uint32_t asb[2] = { smaddr(&As[0][0][0]), smaddr(&As[1][0][0]) };
    uint32_t whb[2] = { smaddr(&Wh[0][0][0]), smaddr(&Wh[1][0][0]) };
    uint32_t wlb[2] = { smaddr(&Wl[0][0][0]), smaddr(&Wl[1][0][0]) };

    float d[2][4][4];
#pragma unroll
    for (int mt = 0; mt < 2; mt++)
#pragma unroll
        for (int nt = 0; nt < 4; nt++)
#pragma unroll
            for (int q = 0; q < 4; q++) d[mt][nt][q] = 0.f;

    dbgemm<4>(d, Ag, m0, 128, 0u, 0, Whg, Wlg, asb, whb, wlb,
              tid, lane, Rm, Cn);

#pragma unroll
    for (int mt = 0; mt < 2; mt++) {
#pragma unroll
        for (int nt = 0; nt < 4; nt++) {
            int col = Cn + nt * 8 + tg * 2;
            float bx = bias[col], by = bias[col + 1];
            int r0 = m0 + Rm + mt * 16 + gid;
            int r1 = r0 + 8;
            if (r0 < N_NODES)
                *(float2*)(C + (size_t)r0 * 64 + col) =
                    make_float2(d[mt][nt][0] + bx, d[mt][nt][1] + by);
            if (r1 < N_NODES)
                *(float2*)(C + (size_t)r1 * 64 + col) =
                    make_float2(d[mt][nt][2] + bx, d[mt][nt][3] + by);
        }
    }
}

// ---------------- host launcher ----------------
extern "C" void kernel_launch(void* const* d_in, const int* in_sizes, int n_in,
                              void* d_out, int out_size) {
    const float* x     = (const float*)d_in[0];
    const void*  ei    = d_in[1];
    const float* gamma = (const float*)d_in[2];
    const float* beta  = (const float*)d_in[3];
    const float* W1 = (const float*)d_in[4];  const float* b1  = (const float*)d_in[5];
    const float* T1 = (const float*)d_in[6];  const float* t1b = (const float*)d_in[7];
    const float* W2 = (const float*)d_in[8];  const float* b2  = (const float*)d_in[9];
    const float* T2 = (const float*)d_in[10]; const float* t2b = (const float*)d_in[11];
    const float* W3 = (const float*)d_in[12]; const float* b3  = (const float*)d_in[13];
    const float* W4 = (const float*)d_in[14]; const float* b4  = (const float*)d_in[15];
    float* out = (float*)d_out;

    __half *x16, *a16, *act, *wthi, *wtlo;
    cudaGetSymbolAddress((void**)&x16,  g_x16);
    cudaGetSymbolAddress((void**)&a16,  g_a16);
    cudaGetSymbolAddress((void**)&act,  g_act);
    cudaGetSymbolAddress((void**)&wthi, g_wthi);
    cudaGetSymbolAddress((void**)&wtlo, g_wtlo);

    const int OT1 = 8192, OW2 = 24576, OT2 = 28672, OW3 = 45056, OW4 = 69632;

    const int EB = (N_EDGES + 255) / 256;
    const int NB = (N_NODES + 255) / 256;   // 391
    const int GB = (N_NODES + 127) / 128;   // 782
    const int PB = N_NODES / 32;            // 3125 (4 nodes/warp, 8 warps/block)

    const int SM_C1 = 38912 + 64  * AST * 2 * 4;  // 59392
    const int SM_C2 = 38912 + 128 * AST * 2 * 4;  // 79872
    cudaFuncSetAttribute(chain_k<0, 64, 256>,
                         cudaFuncAttributeMaxDynamicSharedMemorySize, SM_C1);
    cudaFuncSetAttribute(chain_k<128, 128, 128>,
                         cudaFuncAttributeMaxDynamicSharedMemorySize, SM_C2);

    // fork: weights/BN/L1 on s1, graph preprocessing on stream 0
    cudaStream_t s1;
    cudaStreamCreateWithFlags(&s1, cudaStreamNonBlocking);
    cudaEvent_t e0, e1;
    cudaEventCreateWithFlags(&e0, cudaEventDisableTiming);
    cudaEventCreateWithFlags(&e1, cudaEventDisableTiming);
    cudaEventRecord(e0, 0);
    cudaStreamWaitEvent(s1, e0, 0);

    // ---- stream s1: weights pre-split + BN zero, BN stats, BN final, L1 GEMM ----
    prepw_all_k<<<305, 256, 0, s1>>>(W1, T1, W2, T2, W3, W4, wthi, wtlo);
    bn_stats_k<<<512, 256, 0, s1>>>(x);
    bn_final_k<<<1, 128, 0, s1>>>(gamma, beta);
    tgemm_bn_k<<<GB, 256, 0, s1>>>(x, wthi, wtlo, b1, act);
    cudaEventRecord(e1, s1);

    // ---- stream 0: graph preprocessing ----
    zero_detect_k<<<NB, 256>>>((const int*)ei);
    deg_k<<<EB, 256>>>(ei);
    blkred_dis_k<<<NB, 256>>>();
    partscan_k<<<1, 512>>>(NB);
    blkscan_k<<<NB, 256>>>();
    csrfill_k<<<EB, 256>>>(ei);

    cudaStreamWaitEvent(0, e1, 0);   // join

    // ---- TAGConv1: props fill segs 1..3, then chain (TAG1 + L2) -> h in seg0 ----
    prop_k<<<PB, 256>>>(act,       act + 64);
    prop_k<<<PB, 256>>>(act + 64,  act + 128);
    prop_k<<<PB, 256>>>(act + 128, act + 192);
    chain_k<0, 64, 256><<<GB, 256, SM_C1>>>(
        act, wthi + OT1, wtlo + OT1, t1b,
        nullptr, wthi + OW2, wtlo + OW2, b2, act);

    // ---- TAGConv2: same, then chain (TAG2 + L3 concat x) -> a16 ----
    prop_k<<<PB, 256>>>(act,       act + 64);
    prop_k<<<PB, 256>>>(act + 64,  act + 128);
    prop_k<<<PB, 256>>>(act + 128, act + 192);
    chain_k<128, 128, 128><<<GB, 256, SM_C2>>>(
        act, wthi + OT2, wtlo + OT2, t2b,
        x16, wthi + OW3, wtlo + OW3, b3, a16);

    // ---- layer 4 ----
    tgemm16_k<<<GB, 256>>>(a16, wthi + OW4, wtlo + OW4, b4, out);
}